// round 7
// baseline (speedup 1.0000x reference)
#include <cuda_runtime.h>
#include <cuda_fp16.h>
#include <math.h>
#include <stdint.h>

#define U   1024
#define Bsz 64
#define T   128
#define Dd  256
#define N5  (5*U)        // 5120
#define N3  (3*U)        // 3072
#define KTOT (Dd + 2*U)  // 2304

#define NCTA   120
#define ZSPLIT 3
#define ZKLEN  (KTOT / ZSPLIT)   // 768
#define FSPLIT 12
#define FKLEN  (N3 / FSPLIT)     // 256
#define NTILE  128
#define KCH    64                // K elems per chunk (128 B rows fp16)

// SMEM: rows padded to 144B -> conflict-free ldmatrix
#define ROWB   144
#define A_BLK  (64 * ROWB)             // 9216
#define B_BLK  (128 * ROWB)            // 18432
#define STG_BYTES (A_BLK + B_BLK)      // 27648
#define NSTG   4
#define GSMEM_BYTES (NSTG * STG_BYTES) // 110592

// ---------------- static device scratch --------------------------------------
__device__ __align__(128) __half g_Wt [(size_t)N5 * KTOT];  // W^T fp16 [n][k]
__device__ __align__(128) __half g_AGt[(size_t)U * N3];     // agg^T fp16 [n][k]
__device__ __align__(128) __half g_A16[Bsz * KTOT];         // [x|h|c] fp16
__device__ __align__(128) __half g_O16[Bsz * N3];           // O fp16
__device__ __align__(128) float g_c  [Bsz * U];
__device__ __align__(128) float g_zp [ZSPLIT * Bsz * N5];
__device__ __align__(128) float g_fp [FSPLIT * Bsz * U];
__device__ float g_s[6];
__device__ volatile int g_flags[NCTA];

// ---------------- helpers -----------------------------------------------------
__device__ __forceinline__ float sigf(float x) { return 1.f / (1.f + expf(-x)); }

__device__ __forceinline__ uint32_t smem_u32(const void* p) {
    uint32_t a;
    asm("{ .reg .u64 t; cvta.to.shared.u64 t, %1; cvt.u32.u64 %0, t; }" : "=r"(a) : "l"(p));
    return a;
}
__device__ __forceinline__ void cpasync16(uint32_t s, const void* g) {
    asm volatile("cp.async.cg.shared.global [%0], [%1], 16;" :: "r"(s), "l"(g) : "memory");
}
__device__ __forceinline__ void cp_commit() { asm volatile("cp.async.commit_group;" ::: "memory"); }
template<int N> __device__ __forceinline__ void cp_wait() {
    asm volatile("cp.async.wait_group %0;" :: "n"(N) : "memory");
}
__device__ __forceinline__ void ldsm4(uint32_t* d, uint32_t addr) {
    asm volatile("ldmatrix.sync.aligned.m8n8.x4.shared.b16 {%0,%1,%2,%3}, [%4];"
                 : "=r"(d[0]), "=r"(d[1]), "=r"(d[2]), "=r"(d[3]) : "r"(addr));
}
__device__ __forceinline__ void mma16816(float* c, const uint32_t* a, const uint32_t* b) {
    asm volatile("mma.sync.aligned.m16n8k16.row.col.f32.f16.f16.f32 "
                 "{%0,%1,%2,%3}, {%4,%5,%6,%7}, {%8,%9}, {%0,%1,%2,%3};"
                 : "+f"(c[0]), "+f"(c[1]), "+f"(c[2]), "+f"(c[3])
                 : "r"(a[0]), "r"(a[1]), "r"(a[2]), "r"(a[3]), "r"(b[0]), "r"(b[1]));
}

// global software barrier: all NCTA CTAs co-resident (grid < #SMs)
__device__ __forceinline__ void gbar(int k, int cta, int tid) {
    __syncthreads();
    __threadfence();
    if (tid == 0) g_flags[cta] = k;
    if (tid < NCTA) {
        while (g_flags[tid] < k) __nanosleep(64);
    }
    __threadfence();
    __syncthreads();
}

// ---------------- block reduce helpers ----------------------------------------
__device__ __forceinline__ float blk_reduce_max(float v, float* sm) {
    #pragma unroll
    for (int o = 16; o; o >>= 1) v = fmaxf(v, __shfl_xor_sync(0xffffffffu, v, o));
    int w = threadIdx.x >> 5;
    if ((threadIdx.x & 31) == 0) sm[w] = v;
    __syncthreads();
    float r = sm[0];
    #pragma unroll
    for (int i = 1; i < 8; i++) r = fmaxf(r, sm[i]);
    __syncthreads();
    return r;
}
__device__ __forceinline__ float blk_reduce_sum(float v, float* sm) {
    #pragma unroll
    for (int o = 16; o; o >>= 1) v += __shfl_xor_sync(0xffffffffu, v, o);
    int w = threadIdx.x >> 5;
    if ((threadIdx.x & 31) == 0) sm[w] = v;
    __syncthreads();
    float r = sm[0];
    #pragma unroll
    for (int i = 1; i < 8; i++) r += sm[i];
    __syncthreads();
    return r;
}
struct ScanRes { float excl; float total; };
__device__ __forceinline__ ScanRes blk_scan(float s, float* sm) {
    float ws = s;
    #pragma unroll
    for (int o = 1; o < 32; o <<= 1) {
        float t = __shfl_up_sync(0xffffffffu, ws, o);
        if ((threadIdx.x & 31) >= o) ws += t;
    }
    int w = threadIdx.x >> 5;
    if ((threadIdx.x & 31) == 31) sm[w] = ws;
    __syncthreads();
    float warpBase = 0.f, run = 0.f;
    #pragma unroll
    for (int i = 0; i < 8; i++) { float t = sm[i]; if (i == w) warpBase = run; run += t; }
    __syncthreads();
    ScanRes r; r.excl = warpBase + (ws - s); r.total = run; return r;
}

// ---------------- init kernels -------------------------------------------------
__global__ void ktrans_W(const float* __restrict__ k1, const float* __restrict__ k2,
                         const float* __restrict__ k3) {
    __shared__ float tile[32][33];
    int kt = blockIdx.x * 32, nt = blockIdx.y * 32;
    int tx = threadIdx.x, ty = threadIdx.y;
    #pragma unroll
    for (int i = 0; i < 32; i += 8) {
        int k = kt + ty + i, n = nt + tx;
        const float* src; int kr;
        if (k < Dd) { src = k1; kr = k; }
        else if (k < Dd + U) { src = k2; kr = k - Dd; }
        else { src = k3; kr = k - Dd - U; }
        tile[ty + i][tx] = src[(size_t)kr * N5 + n];
    }
    __syncthreads();
    #pragma unroll
    for (int i = 0; i < 32; i += 8) {
        int n = nt + ty + i, k = kt + tx;
        g_Wt[(size_t)n * KTOT + k] = __float2half(tile[tx][ty + i]);
    }
}
__global__ void ktrans_AG(const float* __restrict__ agg) {
    __shared__ float tile[32][33];
    int kt = blockIdx.x * 32, nt = blockIdx.y * 32;
    int tx = threadIdx.x, ty = threadIdx.y;
    #pragma unroll
    for (int i = 0; i < 32; i += 8)
        tile[ty + i][tx] = agg[(size_t)(kt + ty + i) * U + nt + tx];
    __syncthreads();
    #pragma unroll
    for (int i = 0; i < 32; i += 8) {
        int n = nt + ty + i, k = kt + tx;
        g_AGt[(size_t)n * N3 + k] = __float2half(tile[tx][ty + i]);
    }
}

__global__ void kinit_scalars(const float* a0, const float* b0, const float* a1, const float* b1,
                              const float* a2, const float* b2, const float* a3, const float* b3,
                              const float* a4, const float* b4, const float* a5, const float* b5) {
    __shared__ float sm[8];
    const float* as[6] = {a0, a1, a2, a3, a4, a5};
    const float* bs[6] = {b0, b1, b2, b3, b4, b5};
    for (int p = 0; p < 6; p++) {
        float s = 0.f;
        for (int i = threadIdx.x; i < U; i += 256) s += as[p][i] * bs[p][i];
        float tot = blk_reduce_sum(s, sm);
        if (threadIdx.x == 0) g_s[p] = tot;
        __syncthreads();
    }
}

__global__ void kinit_A(const float* __restrict__ x) {
    int b = blockIdx.x;
    for (int i = threadIdx.x; i < KTOT; i += 256)
        g_A16[b * KTOT + i] = __float2half((i < Dd) ? x[(size_t)(b * T) * Dd + i] : 0.f);
    for (int i = threadIdx.x; i < U; i += 256) g_c[b * U + i] = 0.f;
    if (b == 0) {
        for (int i = threadIdx.x; i < NCTA; i += 256) *((int*)&g_flags[i]) = 0;
    }
}

// ---------------- GEMM phase (device fn) ---------------------------------------
// MODE 0: z (LDK=2304, KLEN=768, +bias ks0) | MODE 1: f (LDK=3072, KLEN=256)
template<int MODE>
__device__ __forceinline__ void gemm_phase(uint32_t smb, int tid, int n0, int ks,
                                           const float* __restrict__ bias) {
    constexpr int LDK  = (MODE == 0) ? KTOT : N3;
    constexpr int NTOT = (MODE == 0) ? N5 : U;
    constexpr int KLEN = (MODE == 0) ? ZKLEN : FKLEN;
    constexpr int NC   = KLEN / KCH;

    const __half* Wp = (MODE == 0) ? g_Wt : g_AGt;
    const __half* Ap = (MODE == 0) ? g_A16 : g_O16;
    float* OUT = (MODE == 0) ? g_zp : g_fp;

    const int kbase = ks * KLEN;
    const int lane  = tid & 31;
    const int w     = tid >> 5;

    // per-thread load descriptors: 1024 segs of 16B per chunk -> 4... (512 A + 1024 W = 1536; 6/thread)
    const __half* srcB[6];
    uint32_t dstO[6];
    #pragma unroll
    for (int i = 0; i < 6; i++) {
        int seg = tid + i * 256;
        if (seg < 512) {
            int r = seg >> 3, s = seg & 7;
            srcB[i] = Ap + (size_t)r * LDK + s * 8;
            dstO[i] = r * ROWB + s * 16;
        } else {
            int idx = seg - 512;
            int r = idx >> 3, s = idx & 7;
            srcB[i] = Wp + (size_t)(n0 + r) * LDK + s * 8;
            dstO[i] = A_BLK + r * ROWB + s * 16;
        }
    }
    auto load_chunk = [&](int kk, int stg) {
        const uint32_t bb = smb + stg * STG_BYTES;
        #pragma unroll
        for (int i = 0; i < 6; i++)
            cpasync16(bb + dstO[i], srcB[i] + kk);
        cp_commit();
    };

    const int mrow0 = (w & 1) * 32;
    const int nrow0 = (w >> 1) * 32;
    const int rA  = mrow0 + (lane & 15);
    const int scA = lane >> 4;
    const int rB  = nrow0 + ((lane >> 4) << 3) + (lane & 7);
    const int scB = (lane >> 3) & 1;

    float acc[2][4][4] = {};

    #pragma unroll
    for (int p = 0; p < 3; p++)
        if (p < NC) load_chunk(kbase + p * KCH, p);

    for (int c = 0; c < NC; c++) {
        int rem = NC - 1 - c;
        if (rem >= 2) cp_wait<2>(); else if (rem == 1) cp_wait<1>(); else cp_wait<0>();
        __syncthreads();
        if (c + 3 < NC) load_chunk(kbase + (c + 3) * KCH, (c + 3) % NSTG);

        const uint32_t bb = smb + (c % NSTG) * STG_BYTES;
        #pragma unroll
        for (int s16 = 0; s16 < 4; s16++) {
            const int kd = s16 * 2;
            uint32_t ah[2][4], bh[2][4];
            #pragma unroll
            for (int mi = 0; mi < 2; mi++)
                ldsm4(ah[mi], bb + (rA + mi * 16) * ROWB + (kd + scA) * 16);
            #pragma unroll
            for (int nj = 0; nj < 2; nj++)
                ldsm4(bh[nj], bb + A_BLK + (rB + nj * 16) * ROWB + (kd + scB) * 16);
            #pragma unroll
            for (int mi = 0; mi < 2; mi++)
                #pragma unroll
                for (int nf = 0; nf < 4; nf++)
                    mma16816(acc[mi][nf], ah[mi], &bh[nf >> 1][(nf & 1) * 2]);
        }
        __syncthreads();
    }

    #pragma unroll
    for (int mi = 0; mi < 2; mi++) {
        #pragma unroll
        for (int nf = 0; nf < 4; nf++) {
            int row = mrow0 + mi * 16 + (lane >> 2);
            int col = n0 + nrow0 + nf * 8 + (lane & 3) * 2;
            float2 v0 = make_float2(acc[mi][nf][0], acc[mi][nf][1]);
            float2 v1 = make_float2(acc[mi][nf][2], acc[mi][nf][3]);
            if (MODE == 0 && ks == 0) {
                v0.x += bias[col]; v0.y += bias[col + 1];
                v1.x += bias[col]; v1.y += bias[col + 1];
            }
            *reinterpret_cast<float2*>(OUT + (size_t)(ks * Bsz + row) * NTOT + col) = v0;
            *reinterpret_cast<float2*>(OUT + (size_t)(ks * Bsz + row + 8) * NTOT + col) = v1;
        }
    }
}

// ---------------- gate phase (device fn, one CTA per batch row) -----------------
__device__ __forceinline__ void gate_phase(int b, int tid) {
    __shared__ float sm[16];
    const int i0 = tid * 4;

    float uz[4], dz[4], rz[4];
    {
        #define LOAD3(off, out) {                                                   \
            float4 s0 = *reinterpret_cast<const float4*>(g_zp + (size_t)(0*Bsz+b)*N5 + (off)); \
            float4 s1 = *reinterpret_cast<const float4*>(g_zp + (size_t)(1*Bsz+b)*N5 + (off)); \
            float4 s2 = *reinterpret_cast<const float4*>(g_zp + (size_t)(2*Bsz+b)*N5 + (off)); \
            out[0] = s0.x + s1.x + s2.x; out[1] = s0.y + s1.y + s2.y;                  \
            out[2] = s0.z + s1.z + s2.z; out[3] = s0.w + s1.w + s2.w; }
        LOAD3(i0,         uz)
        LOAD3(U + i0,     dz)
        LOAD3(2 * U + i0, rz)
        #undef LOAD3
    }

    float mx = fmaxf(fmaxf(uz[0], uz[1]), fmaxf(uz[2], uz[3]));
    mx = blk_reduce_max(mx, sm);
    float e[4], ls = 0.f;
    #pragma unroll
    for (int l = 0; l < 4; l++) { e[l] = expf(uz[l] - mx); ls += e[l]; }
    ScanRes s1 = blk_scan(ls, sm);
    float up[4];
    { float P = s1.excl, inv = 1.f / s1.total;
      #pragma unroll
      for (int l = 0; l < 4; l++) { P += e[l]; up[l] = P * inv; } }

    float mx2 = fmaxf(fmaxf(dz[0], dz[1]), fmaxf(dz[2], dz[3]));
    mx2 = blk_reduce_max(mx2, sm);
    float ed[4]; ls = 0.f;
    #pragma unroll
    for (int l = 0; l < 4; l++) { ed[l] = expf(dz[l] - mx2); ls += ed[l]; }
    ScanRes s2 = blk_scan(ls, sm);
    float dn[4];
    { float P = s2.excl, inv = 1.f / s2.total;
      #pragma unroll
      for (int l = 0; l < 4; l++) { P += ed[l]; dn[l] = (s2.total - P + ed[l]) * inv; } }

    float pdu = 0.f, pru = 0.f, pdr = 0.f;
    #pragma unroll
    for (int l = 0; l < 4; l++) { pdu += dn[l] * up[l]; pru += rz[l] * up[l]; pdr += dn[l] * rz[l]; }
    float du = blk_reduce_sum(pdu, sm);
    float ru = blk_reduce_sum(pru, sm);
    float dr = blk_reduce_sum(pdr, sm);

    const float s_ud = g_s[0], s_ur = g_s[1], s_ru = g_s[2];
    const float s_rd = g_s[3], s_du = g_s[4], s_dr = g_s[5];

    #pragma unroll
    for (int l = 0; l < 4; l++) {
        float t1 = sigf(s_ud * up[l] * du) + sigf(s_ur * up[l] * ru);
        float t2 = sigf(s_ru * rz[l] * ru) + sigf(s_rd * rz[l] * dr);
        float t3 = sigf(s_du * dn[l] * du) + sigf(s_dr * dn[l] * dr);
        g_O16[b * N3 + i0 + l]         = __float2half(t1);
        g_O16[b * N3 + U + i0 + l]     = __float2half(t2);
        g_O16[b * N3 + 2 * U + i0 + l] = __float2half(t3);
    }
}

// ---------------- update phase (device fn, one CTA per batch row) ---------------
__device__ __forceinline__ void update_phase(int b, int tid, int t,
                                             const float* __restrict__ x,
                                             float* __restrict__ out) {
    const int j0 = tid * 4;
    #pragma unroll
    for (int l = 0; l < 4; l++) {
        int j = j0 + l;
        float fs = 0.f;
        #pragma unroll
        for (int ks = 0; ks < FSPLIT; ks++) fs += g_fp[(size_t)(ks * Bsz + b) * U + j];
        float f = sigf(fs);
        float og = 0.f, zc = 0.f;
        #pragma unroll
        for (int ks = 0; ks < ZSPLIT; ks++) {
            og += g_zp[(size_t)(ks * Bsz + b) * N5 + 3 * U + j];
            zc += g_zp[(size_t)(ks * Bsz + b) * N5 + 4 * U + j];
        }
        float ci = tanhf(zc);
        float co = g_c[b * U + j];
        float cn = f * co + (1.f - f) * ci;
        float hn = og * tanhf(cn);
        g_c[b * U + j] = cn;
        out[((size_t)b * T + t) * U + j] = hn;
        g_A16[b * KTOT + Dd + j]     = __float2half(hn);
        g_A16[b * KTOT + Dd + U + j] = __float2half(cn);
    }
    if (t + 1 < T && tid < 64) {
        #pragma unroll
        for (int l = 0; l < 4; l++) {
            int d = tid * 4 + l;
            g_A16[b * KTOT + d] = __float2half(x[((size_t)b * T + (t + 1)) * Dd + d]);
        }
    }
}

// ---------------- persistent scan kernel ----------------------------------------
__global__ void __launch_bounds__(256) scan_kernel(const float* __restrict__ x,
                                                   const float* __restrict__ bias,
                                                   float* __restrict__ out) {
    const int cta = blockIdx.x, tid = threadIdx.x;
    extern __shared__ char dyn[];
    const uint32_t smb = smem_u32(dyn);

    const int n0z = (cta % 40) * NTILE, ksz = cta / 40;         // 40 x 3
    const int n0f = (cta % 8) * NTILE,  ksf = cta / 8;          // 8 x 12 (cta < 96)

    int k = 0;
    for (int t = 0; t < T; t++) {
        gemm_phase<0>(smb, tid, n0z, ksz, bias);
        gbar(++k, cta, tid);
        if (cta < Bsz) gate_phase(cta, tid);
        gbar(++k, cta, tid);
        if (cta < 96) gemm_phase<1>(smb, tid, n0f, ksf, nullptr);
        gbar(++k, cta, tid);
        if (cta < Bsz) update_phase(cta, tid, t, x, out);
        gbar(++k, cta, tid);
    }
}

// ---------------- launch ---------------------------------------------------------
extern "C" void kernel_launch(void* const* d_in, const int* in_sizes, int n_in,
                              void* d_out, int out_size) {
    const float* x    = (const float*)d_in[0];
    const float* kern = (const float*)d_in[1];
    const float* rker = (const float*)d_in[2];
    const float* cker = (const float*)d_in[3];
    const float* bias = (const float*)d_in[4];
    const float* agg  = (const float*)d_in[5];
    float* out = (float*)d_out;

    cudaFuncSetAttribute(scan_kernel, cudaFuncAttributeMaxDynamicSharedMemorySize, GSMEM_BYTES);

    ktrans_W <<<dim3(KTOT / 32, N5 / 32), dim3(32, 8)>>>(kern, rker, cker);
    ktrans_AG<<<dim3(N3 / 32,  U  / 32), dim3(32, 8)>>>(agg);
    kinit_scalars<<<1, 256>>>((const float*)d_in[6],  (const float*)d_in[7],
                              (const float*)d_in[8],  (const float*)d_in[9],
                              (const float*)d_in[10], (const float*)d_in[11],
                              (const float*)d_in[12], (const float*)d_in[13],
                              (const float*)d_in[14], (const float*)d_in[15],
                              (const float*)d_in[16], (const float*)d_in[17]);
    kinit_A<<<Bsz, 256>>>(x);

    scan_kernel<<<NCTA, 256, GSMEM_BYTES>>>(x, bias, out);
}

// round 8
// speedup vs baseline: 1.5169x; 1.5169x over previous
#include <cuda_runtime.h>
#include <cuda_fp16.h>
#include <math.h>
#include <stdint.h>

#define U   1024
#define Bsz 64
#define T   128
#define Dd  256
#define N5  (5*U)        // 5120
#define N3  (3*U)        // 3072
#define KTOT (Dd + 2*U)  // 2304

#define ZSPLIT 3
#define ZKLEN  (KTOT / ZSPLIT)   // 768
#define FSPLIT 12
#define FKLEN  (N3 / FSPLIT)     // 256
#define NTILE  128
#define KCH    64                // K elems per chunk (128 B rows fp16)

// SMEM: rows padded to 144B -> conflict-free ldmatrix
#define ROWB   144
#define A_BLK  (64 * ROWB)             // 9216
#define B_BLK  (128 * ROWB)            // 18432
#define STG_BYTES (A_BLK + B_BLK)      // 27648
#define NSTG   4
#define GSMEM_BYTES (NSTG * STG_BYTES) // 110592

// ---------------- static device scratch --------------------------------------
__device__ __align__(128) __half g_Wt [(size_t)N5 * KTOT];  // W^T fp16 [n][k]
__device__ __align__(128) __half g_AGt[(size_t)U * N3];     // agg^T fp16 [n][k]
__device__ __align__(128) __half g_A16[Bsz * KTOT];         // [x|h|c] fp16
__device__ __align__(128) __half g_O16[Bsz * N3];           // O fp16
__device__ __align__(128) float g_c  [Bsz * U];
__device__ __align__(128) float g_zp [ZSPLIT * Bsz * N5];
__device__ __align__(128) float g_fp [FSPLIT * Bsz * U];
__device__ float g_s[6];
__device__ unsigned g_cnt[U / NTILE];   // per-N-tile arrival counters (epoch-modulo)

// ---------------- helpers -----------------------------------------------------
__device__ __forceinline__ float sigf(float x) { return 1.f / (1.f + expf(-x)); }

__device__ __forceinline__ uint32_t smem_u32(const void* p) {
    uint32_t a;
    asm("{ .reg .u64 t; cvta.to.shared.u64 t, %1; cvt.u32.u64 %0, t; }" : "=r"(a) : "l"(p));
    return a;
}
__device__ __forceinline__ void cpasync16(uint32_t s, const void* g) {
    asm volatile("cp.async.cg.shared.global [%0], [%1], 16;" :: "r"(s), "l"(g) : "memory");
}
__device__ __forceinline__ void cp_commit() { asm volatile("cp.async.commit_group;" ::: "memory"); }
template<int N> __device__ __forceinline__ void cp_wait() {
    asm volatile("cp.async.wait_group %0;" :: "n"(N) : "memory");
}
__device__ __forceinline__ void ldsm4(uint32_t* d, uint32_t addr) {
    asm volatile("ldmatrix.sync.aligned.m8n8.x4.shared.b16 {%0,%1,%2,%3}, [%4];"
                 : "=r"(d[0]), "=r"(d[1]), "=r"(d[2]), "=r"(d[3]) : "r"(addr));
}
__device__ __forceinline__ void mma16816(float* c, const uint32_t* a, const uint32_t* b) {
    asm volatile("mma.sync.aligned.m16n8k16.row.col.f32.f16.f16.f32 "
                 "{%0,%1,%2,%3}, {%4,%5,%6,%7}, {%8,%9}, {%0,%1,%2,%3};"
                 : "+f"(c[0]), "+f"(c[1]), "+f"(c[2]), "+f"(c[3])
                 : "r"(a[0]), "r"(a[1]), "r"(a[2]), "r"(a[3]), "r"(b[0]), "r"(b[1]));
}

// ---------------- block reduce helpers ----------------------------------------
__device__ __forceinline__ float blk_reduce_max(float v, float* sm) {
    #pragma unroll
    for (int o = 16; o; o >>= 1) v = fmaxf(v, __shfl_xor_sync(0xffffffffu, v, o));
    int w = threadIdx.x >> 5;
    if ((threadIdx.x & 31) == 0) sm[w] = v;
    __syncthreads();
    float r = sm[0];
    #pragma unroll
    for (int i = 1; i < 8; i++) r = fmaxf(r, sm[i]);
    __syncthreads();
    return r;
}
__device__ __forceinline__ float blk_reduce_sum(float v, float* sm) {
    #pragma unroll
    for (int o = 16; o; o >>= 1) v += __shfl_xor_sync(0xffffffffu, v, o);
    int w = threadIdx.x >> 5;
    if ((threadIdx.x & 31) == 0) sm[w] = v;
    __syncthreads();
    float r = sm[0];
    #pragma unroll
    for (int i = 1; i < 8; i++) r += sm[i];
    __syncthreads();
    return r;
}
struct ScanRes { float excl; float total; };
__device__ __forceinline__ ScanRes blk_scan(float s, float* sm) {
    float ws = s;
    #pragma unroll
    for (int o = 1; o < 32; o <<= 1) {
        float t = __shfl_up_sync(0xffffffffu, ws, o);
        if ((threadIdx.x & 31) >= o) ws += t;
    }
    int w = threadIdx.x >> 5;
    if ((threadIdx.x & 31) == 31) sm[w] = ws;
    __syncthreads();
    float warpBase = 0.f, run = 0.f;
    #pragma unroll
    for (int i = 0; i < 8; i++) { float t = sm[i]; if (i == w) warpBase = run; run += t; }
    __syncthreads();
    ScanRes r; r.excl = warpBase + (ws - s); r.total = run; return r;
}

// ---------------- init kernels -------------------------------------------------
__global__ void ktrans_W(const float* __restrict__ k1, const float* __restrict__ k2,
                         const float* __restrict__ k3) {
    __shared__ float tile[32][33];
    int kt = blockIdx.x * 32, nt = blockIdx.y * 32;
    int tx = threadIdx.x, ty = threadIdx.y;
    #pragma unroll
    for (int i = 0; i < 32; i += 8) {
        int k = kt + ty + i, n = nt + tx;
        const float* src; int kr;
        if (k < Dd) { src = k1; kr = k; }
        else if (k < Dd + U) { src = k2; kr = k - Dd; }
        else { src = k3; kr = k - Dd - U; }
        tile[ty + i][tx] = src[(size_t)kr * N5 + n];
    }
    __syncthreads();
    #pragma unroll
    for (int i = 0; i < 32; i += 8) {
        int n = nt + ty + i, k = kt + tx;
        g_Wt[(size_t)n * KTOT + k] = __float2half(tile[tx][ty + i]);
    }
}
__global__ void ktrans_AG(const float* __restrict__ agg) {
    __shared__ float tile[32][33];
    int kt = blockIdx.x * 32, nt = blockIdx.y * 32;
    int tx = threadIdx.x, ty = threadIdx.y;
    #pragma unroll
    for (int i = 0; i < 32; i += 8)
        tile[ty + i][tx] = agg[(size_t)(kt + ty + i) * U + nt + tx];
    __syncthreads();
    #pragma unroll
    for (int i = 0; i < 32; i += 8) {
        int n = nt + ty + i, k = kt + tx;
        g_AGt[(size_t)n * N3 + k] = __float2half(tile[tx][ty + i]);
    }
}

__global__ void kinit_scalars(const float* a0, const float* b0, const float* a1, const float* b1,
                              const float* a2, const float* b2, const float* a3, const float* b3,
                              const float* a4, const float* b4, const float* a5, const float* b5) {
    __shared__ float sm[8];
    const float* as[6] = {a0, a1, a2, a3, a4, a5};
    const float* bs[6] = {b0, b1, b2, b3, b4, b5};
    for (int p = 0; p < 6; p++) {
        float s = 0.f;
        for (int i = threadIdx.x; i < U; i += 256) s += as[p][i] * bs[p][i];
        float tot = blk_reduce_sum(s, sm);
        if (threadIdx.x == 0) g_s[p] = tot;
        __syncthreads();
    }
}

__global__ void kinit_A(const float* __restrict__ x) {
    int b = blockIdx.x;
    for (int i = threadIdx.x; i < KTOT; i += 256)
        g_A16[b * KTOT + i] = __float2half((i < Dd) ? x[(size_t)(b * T) * Dd + i] : 0.f);
    for (int i = threadIdx.x; i < U; i += 256) g_c[b * U + i] = 0.f;
    if (b == 0 && threadIdx.x < U / NTILE) g_cnt[threadIdx.x] = 0u;
}

// ---------------- z GEMM (MODE 0 of old kernel) --------------------------------
__global__ void __launch_bounds__(256) zgemm(const float* __restrict__ bias) {
    constexpr int LDK  = KTOT;
    constexpr int NC   = ZKLEN / KCH;   // 12

    const int n0    = blockIdx.x * NTILE;
    const int ks    = blockIdx.y;
    const int kbase = ks * ZKLEN;
    const int tid   = threadIdx.x;
    const int lane  = tid & 31;
    const int w     = tid >> 5;

    extern __shared__ char dyn[];
    const uint32_t smb = smem_u32(dyn);

    const __half* srcB[6];
    uint32_t dstO[6];
    #pragma unroll
    for (int i = 0; i < 6; i++) {
        int seg = tid + i * 256;
        if (seg < 512) {
            int r = seg >> 3, s = seg & 7;
            srcB[i] = g_A16 + (size_t)r * LDK + s * 8;
            dstO[i] = r * ROWB + s * 16;
        } else {
            int idx = seg - 512;
            int r = idx >> 3, s = idx & 7;
            srcB[i] = g_Wt + (size_t)(n0 + r) * LDK + s * 8;
            dstO[i] = A_BLK + r * ROWB + s * 16;
        }
    }
    auto load_chunk = [&](int kk, int stg) {
        const uint32_t bb = smb + stg * STG_BYTES;
        #pragma unroll
        for (int i = 0; i < 6; i++)
            cpasync16(bb + dstO[i], srcB[i] + kk);
        cp_commit();
    };

    const int mrow0 = (w & 1) * 32;
    const int nrow0 = (w >> 1) * 32;
    const int rA  = mrow0 + (lane & 15);
    const int scA = lane >> 4;
    const int rB  = nrow0 + ((lane >> 4) << 3) + (lane & 7);
    const int scB = (lane >> 3) & 1;

    float acc[2][4][4] = {};

    #pragma unroll
    for (int p = 0; p < 3; p++)
        if (p < NC) load_chunk(kbase + p * KCH, p);

    for (int c = 0; c < NC; c++) {
        int rem = NC - 1 - c;
        if (rem >= 2) cp_wait<2>(); else if (rem == 1) cp_wait<1>(); else cp_wait<0>();
        __syncthreads();
        if (c + 3 < NC) load_chunk(kbase + (c + 3) * KCH, (c + 3) % NSTG);

        const uint32_t bb = smb + (c % NSTG) * STG_BYTES;
        #pragma unroll
        for (int s16 = 0; s16 < 4; s16++) {
            const int kd = s16 * 2;
            uint32_t ah[2][4], bh[2][4];
            #pragma unroll
            for (int mi = 0; mi < 2; mi++)
                ldsm4(ah[mi], bb + (rA + mi * 16) * ROWB + (kd + scA) * 16);
            #pragma unroll
            for (int nj = 0; nj < 2; nj++)
                ldsm4(bh[nj], bb + A_BLK + (rB + nj * 16) * ROWB + (kd + scB) * 16);
            #pragma unroll
            for (int mi = 0; mi < 2; mi++)
                #pragma unroll
                for (int nf = 0; nf < 4; nf++)
                    mma16816(acc[mi][nf], ah[mi], &bh[nf >> 1][(nf & 1) * 2]);
        }
        __syncthreads();
    }

    #pragma unroll
    for (int mi = 0; mi < 2; mi++) {
        #pragma unroll
        for (int nf = 0; nf < 4; nf++) {
            int row = mrow0 + mi * 16 + (lane >> 2);
            int col = n0 + nrow0 + nf * 8 + (lane & 3) * 2;
            float2 v0 = make_float2(acc[mi][nf][0], acc[mi][nf][1]);
            float2 v1 = make_float2(acc[mi][nf][2], acc[mi][nf][3]);
            if (ks == 0) {
                v0.x += bias[col]; v0.y += bias[col + 1];
                v1.x += bias[col]; v1.y += bias[col + 1];
            }
            *reinterpret_cast<float2*>(g_zp + (size_t)(ks * Bsz + row) * N5 + col) = v0;
            *reinterpret_cast<float2*>(g_zp + (size_t)(ks * Bsz + row + 8) * N5 + col) = v1;
        }
    }
}

// ---------------- gate kernel ---------------------------------------------------
__global__ void __launch_bounds__(256) kb() {
    __shared__ float sm[16];
    const int b = blockIdx.x, tid = threadIdx.x;
    const int i0 = tid * 4;

    float uz[4], dz[4], rz[4];
    {
        #define LOAD3(off, out) {                                                   \
            float4 s0 = *reinterpret_cast<const float4*>(g_zp + (size_t)(0*Bsz+b)*N5 + (off)); \
            float4 s1 = *reinterpret_cast<const float4*>(g_zp + (size_t)(1*Bsz+b)*N5 + (off)); \
            float4 s2 = *reinterpret_cast<const float4*>(g_zp + (size_t)(2*Bsz+b)*N5 + (off)); \
            out[0] = s0.x + s1.x + s2.x; out[1] = s0.y + s1.y + s2.y;                  \
            out[2] = s0.z + s1.z + s2.z; out[3] = s0.w + s1.w + s2.w; }
        LOAD3(i0,         uz)
        LOAD3(U + i0,     dz)
        LOAD3(2 * U + i0, rz)
        #undef LOAD3
    }

    float mx = fmaxf(fmaxf(uz[0], uz[1]), fmaxf(uz[2], uz[3]));
    mx = blk_reduce_max(mx, sm);
    float e[4], ls = 0.f;
    #pragma unroll
    for (int l = 0; l < 4; l++) { e[l] = expf(uz[l] - mx); ls += e[l]; }
    ScanRes s1 = blk_scan(ls, sm);
    float up[4];
    { float P = s1.excl, inv = 1.f / s1.total;
      #pragma unroll
      for (int l = 0; l < 4; l++) { P += e[l]; up[l] = P * inv; } }

    float mx2 = fmaxf(fmaxf(dz[0], dz[1]), fmaxf(dz[2], dz[3]));
    mx2 = blk_reduce_max(mx2, sm);
    float ed[4]; ls = 0.f;
    #pragma unroll
    for (int l = 0; l < 4; l++) { ed[l] = expf(dz[l] - mx2); ls += ed[l]; }
    ScanRes s2 = blk_scan(ls, sm);
    float dn[4];
    { float P = s2.excl, inv = 1.f / s2.total;
      #pragma unroll
      for (int l = 0; l < 4; l++) { P += ed[l]; dn[l] = (s2.total - P + ed[l]) * inv; } }

    float pdu = 0.f, pru = 0.f, pdr = 0.f;
    #pragma unroll
    for (int l = 0; l < 4; l++) { pdu += dn[l] * up[l]; pru += rz[l] * up[l]; pdr += dn[l] * rz[l]; }
    float du = blk_reduce_sum(pdu, sm);
    float ru = blk_reduce_sum(pru, sm);
    float dr = blk_reduce_sum(pdr, sm);

    const float s_ud = g_s[0], s_ur = g_s[1], s_ru = g_s[2];
    const float s_rd = g_s[3], s_du = g_s[4], s_dr = g_s[5];

    #pragma unroll
    for (int l = 0; l < 4; l++) {
        float t1 = sigf(s_ud * up[l] * du) + sigf(s_ur * up[l] * ru);
        float t2 = sigf(s_ru * rz[l] * ru) + sigf(s_rd * rz[l] * dr);
        float t3 = sigf(s_du * dn[l] * du) + sigf(s_dr * dn[l] * dr);
        g_O16[b * N3 + i0 + l]         = __float2half(t1);
        g_O16[b * N3 + U + i0 + l]     = __float2half(t2);
        g_O16[b * N3 + 2 * U + i0 + l] = __float2half(t3);
    }
}

// ---------------- fused agg GEMM + state update ---------------------------------
// grid (U/NTILE, FSPLIT) = (8, 12). Each CTA writes its split-K partial, then the
// last-arriving CTA per N-tile performs the cell/hidden update for that j-slice.
__global__ void __launch_bounds__(256) fgemm_update(const float* __restrict__ x,
                                                    float* __restrict__ out, int t) {
    constexpr int LDK = N3;
    constexpr int NC  = FKLEN / KCH;   // 4

    const int n0    = blockIdx.x * NTILE;
    const int ks    = blockIdx.y;
    const int kbase = ks * FKLEN;
    const int tid   = threadIdx.x;
    const int lane  = tid & 31;
    const int w     = tid >> 5;

    extern __shared__ char dyn[];
    const uint32_t smb = smem_u32(dyn);

    const __half* srcB[6];
    uint32_t dstO[6];
    #pragma unroll
    for (int i = 0; i < 6; i++) {
        int seg = tid + i * 256;
        if (seg < 512) {
            int r = seg >> 3, s = seg & 7;
            srcB[i] = g_O16 + (size_t)r * LDK + s * 8;
            dstO[i] = r * ROWB + s * 16;
        } else {
            int idx = seg - 512;
            int r = idx >> 3, s = idx & 7;
            srcB[i] = g_AGt + (size_t)(n0 + r) * LDK + s * 8;
            dstO[i] = A_BLK + r * ROWB + s * 16;
        }
    }
    auto load_chunk = [&](int kk, int stg) {
        const uint32_t bb = smb + stg * STG_BYTES;
        #pragma unroll
        for (int i = 0; i < 6; i++)
            cpasync16(bb + dstO[i], srcB[i] + kk);
        cp_commit();
    };

    const int mrow0 = (w & 1) * 32;
    const int nrow0 = (w >> 1) * 32;
    const int rA  = mrow0 + (lane & 15);
    const int scA = lane >> 4;
    const int rB  = nrow0 + ((lane >> 4) << 3) + (lane & 7);
    const int scB = (lane >> 3) & 1;

    float acc[2][4][4] = {};

    #pragma unroll
    for (int p = 0; p < 3; p++)
        if (p < NC) load_chunk(kbase + p * KCH, p);

    for (int c = 0; c < NC; c++) {
        int rem = NC - 1 - c;
        if (rem >= 2) cp_wait<2>(); else if (rem == 1) cp_wait<1>(); else cp_wait<0>();
        __syncthreads();
        if (c + 3 < NC) load_chunk(kbase + (c + 3) * KCH, (c + 3) % NSTG);

        const uint32_t bb = smb + (c % NSTG) * STG_BYTES;
        #pragma unroll
        for (int s16 = 0; s16 < 4; s16++) {
            const int kd = s16 * 2;
            uint32_t ah[2][4], bh[2][4];
            #pragma unroll
            for (int mi = 0; mi < 2; mi++)
                ldsm4(ah[mi], bb + (rA + mi * 16) * ROWB + (kd + scA) * 16);
            #pragma unroll
            for (int nj = 0; nj < 2; nj++)
                ldsm4(bh[nj], bb + A_BLK + (rB + nj * 16) * ROWB + (kd + scB) * 16);
            #pragma unroll
            for (int mi = 0; mi < 2; mi++)
                #pragma unroll
                for (int nf = 0; nf < 4; nf++)
                    mma16816(acc[mi][nf], ah[mi], &bh[nf >> 1][(nf & 1) * 2]);
        }
        __syncthreads();
    }

    #pragma unroll
    for (int mi = 0; mi < 2; mi++) {
        #pragma unroll
        for (int nf = 0; nf < 4; nf++) {
            int row = mrow0 + mi * 16 + (lane >> 2);
            int col = n0 + nrow0 + nf * 8 + (lane & 3) * 2;
            *reinterpret_cast<float2*>(g_fp + (size_t)(ks * Bsz + row) * U + col) =
                make_float2(acc[mi][nf][0], acc[mi][nf][1]);
            *reinterpret_cast<float2*>(g_fp + (size_t)(ks * Bsz + row + 8) * U + col) =
                make_float2(acc[mi][nf][2], acc[mi][nf][3]);
        }
    }

    // ---- last-CTA-per-tile state update ----
    __threadfence();
    __syncthreads();
    __shared__ unsigned s_old;
    if (tid == 0) s_old = atomicAdd(&g_cnt[blockIdx.x], 1u);
    __syncthreads();
    if ((s_old + 1) % FSPLIT != 0) return;
    __threadfence();

    const int jl = (tid & 31) * 4;          // 0..124
    const int bg = tid >> 5;                // 0..7
    #pragma unroll
    for (int rb = 0; rb < 8; rb++) {
        const int b = bg * 8 + rb;
        const int j = n0 + jl;
        float4 fs = make_float4(0.f, 0.f, 0.f, 0.f);
        #pragma unroll
        for (int kq = 0; kq < FSPLIT; kq++) {
            float4 p = *reinterpret_cast<const float4*>(g_fp + (size_t)(kq * Bsz + b) * U + j);
            fs.x += p.x; fs.y += p.y; fs.z += p.z; fs.w += p.w;
        }
        float4 og = make_float4(0.f, 0.f, 0.f, 0.f), zc = og;
        #pragma unroll
        for (int kq = 0; kq < ZSPLIT; kq++) {
            float4 p = *reinterpret_cast<const float4*>(g_zp + (size_t)(kq * Bsz + b) * N5 + 3 * U + j);
            og.x += p.x; og.y += p.y; og.z += p.z; og.w += p.w;
            p = *reinterpret_cast<const float4*>(g_zp + (size_t)(kq * Bsz + b) * N5 + 4 * U + j);
            zc.x += p.x; zc.y += p.y; zc.z += p.z; zc.w += p.w;
        }
        float fv[4] = {fs.x, fs.y, fs.z, fs.w};
        float ov[4] = {og.x, og.y, og.z, og.w};
        float zv[4] = {zc.x, zc.y, zc.z, zc.w};
        float4 co = *reinterpret_cast<const float4*>(g_c + (size_t)b * U + j);
        float cv[4] = {co.x, co.y, co.z, co.w};
        float cn[4], hn[4];
        #pragma unroll
        for (int l = 0; l < 4; l++) {
            float f  = sigf(fv[l]);
            float ci = tanhf(zv[l]);
            cn[l] = f * cv[l] + (1.f - f) * ci;
            hn[l] = ov[l] * tanhf(cn[l]);
        }
        *reinterpret_cast<float4*>(g_c + (size_t)b * U + j) = make_float4(cn[0], cn[1], cn[2], cn[3]);
        *reinterpret_cast<float4*>(out + ((size_t)b * T + t) * U + j) = make_float4(hn[0], hn[1], hn[2], hn[3]);
        __half2* hA = reinterpret_cast<__half2*>(g_A16 + (size_t)b * KTOT + Dd + j);
        hA[0] = __floats2half2_rn(hn[0], hn[1]);
        hA[1] = __floats2half2_rn(hn[2], hn[3]);
        __half2* cA = reinterpret_cast<__half2*>(g_A16 + (size_t)b * KTOT + Dd + U + j);
        cA[0] = __floats2half2_rn(cn[0], cn[1]);
        cA[1] = __floats2half2_rn(cn[2], cn[3]);
    }
    // next-step x into A (tiles covering dims 0..255)
    if (t + 1 < T && n0 < Dd) {
        // 64 rows x 128 cols = 8192 elems / 256 thr = 32 each
        const int jc = (tid & 31) * 4;     // col group within tile
        const int bg2 = tid >> 5;
        #pragma unroll
        for (int rb = 0; rb < 8; rb++) {
            const int b = bg2 * 8 + rb;
            const int d = n0 + jc;
            float4 xv = *reinterpret_cast<const float4*>(x + ((size_t)b * T + (t + 1)) * Dd + d);
            __half2* dA = reinterpret_cast<__half2*>(g_A16 + (size_t)b * KTOT + d);
            dA[0] = __floats2half2_rn(xv.x, xv.y);
            dA[1] = __floats2half2_rn(xv.z, xv.w);
        }
    }
}

// ---------------- launch ---------------------------------------------------------
extern "C" void kernel_launch(void* const* d_in, const int* in_sizes, int n_in,
                              void* d_out, int out_size) {
    const float* x    = (const float*)d_in[0];
    const float* kern = (const float*)d_in[1];
    const float* rker = (const float*)d_in[2];
    const float* cker = (const float*)d_in[3];
    const float* bias = (const float*)d_in[4];
    const float* agg  = (const float*)d_in[5];
    float* out = (float*)d_out;

    cudaFuncSetAttribute(zgemm, cudaFuncAttributeMaxDynamicSharedMemorySize, GSMEM_BYTES);
    cudaFuncSetAttribute(fgemm_update, cudaFuncAttributeMaxDynamicSharedMemorySize, GSMEM_BYTES);

    ktrans_W <<<dim3(KTOT / 32, N5 / 32), dim3(32, 8)>>>(kern, rker, cker);
    ktrans_AG<<<dim3(N3 / 32,  U  / 32), dim3(32, 8)>>>(agg);
    kinit_scalars<<<1, 256>>>((const float*)d_in[6],  (const float*)d_in[7],
                              (const float*)d_in[8],  (const float*)d_in[9],
                              (const float*)d_in[10], (const float*)d_in[11],
                              (const float*)d_in[12], (const float*)d_in[13],
                              (const float*)d_in[14], (const float*)d_in[15],
                              (const float*)d_in[16], (const float*)d_in[17]);
    kinit_A<<<Bsz, 256>>>(x);

    for (int t = 0; t < T; t++) {
        zgemm<<<dim3(N5 / NTILE, ZSPLIT), 256, GSMEM_BYTES>>>(bias);
        kb<<<Bsz, 256>>>();
        fgemm_update<<<dim3(U / NTILE, FSPLIT), 256, GSMEM_BYTES>>>(x, out, t);
    }
}

// round 9
// speedup vs baseline: 2.1504x; 1.4176x over previous
#include <cuda_runtime.h>
#include <cuda_fp16.h>
#include <math.h>
#include <stdint.h>

#define U   1024
#define Bsz 64
#define T   128
#define Dd  256
#define N5  (5*U)        // 5120
#define N3  (3*U)        // 3072
#define KTOT (Dd + 2*U)  // 2304

#define ZSPLIT 3
#define ZKLEN  (KTOT / ZSPLIT)   // 768
#define FSPLIT 8
#define FKLEN  (N3 / FSPLIT)     // 384
#define NTILE  128
#define KCH    64                // K elems per chunk (128 B rows fp16)
#define ZCTAS  (N5 / NTILE * ZSPLIT)   // 120
#define FCTAS  (U / NTILE * FSPLIT)    // 64

// SMEM: rows padded to 144B -> conflict-free ldmatrix
#define ROWB   144
#define A_BLK  (64 * ROWB)             // 9216
#define B_BLK  (128 * ROWB)            // 18432
#define STG_BYTES (A_BLK + B_BLK)      // 27648
#define NSTG   4
#define GSMEM_BYTES (NSTG * STG_BYTES) // 110592

// ---------------- static device scratch --------------------------------------
__device__ __align__(128) __half g_Wt [(size_t)N5 * KTOT];  // W^T fp16 [n][k]
__device__ __align__(128) __half g_AGt[(size_t)U * N3];     // agg^T fp16 [n][k]
__device__ __align__(128) __half g_A16[Bsz * KTOT];         // [x|h|c] fp16
__device__ __align__(128) __half g_O16[Bsz * N3];           // O fp16
__device__ __align__(128) float g_c  [Bsz * U];
__device__ __align__(128) float g_zp [ZSPLIT * Bsz * N5];
__device__ __align__(128) float g_fp [FSPLIT * Bsz * U];
__device__ float g_s[6];
__device__ unsigned g_zcnt[T];
__device__ unsigned g_fcnt[T];

// ---------------- helpers -----------------------------------------------------
__device__ __forceinline__ float sigf(float x) { return 1.f / (1.f + expf(-x)); }

__device__ __forceinline__ uint32_t smem_u32(const void* p) {
    uint32_t a;
    asm("{ .reg .u64 t; cvta.to.shared.u64 t, %1; cvt.u32.u64 %0, t; }" : "=r"(a) : "l"(p));
    return a;
}
__device__ __forceinline__ void cpasync16(uint32_t s, const void* g) {
    asm volatile("cp.async.cg.shared.global [%0], [%1], 16;" :: "r"(s), "l"(g) : "memory");
}
__device__ __forceinline__ void cp_commit() { asm volatile("cp.async.commit_group;" ::: "memory"); }
template<int N> __device__ __forceinline__ void cp_wait() {
    asm volatile("cp.async.wait_group %0;" :: "n"(N) : "memory");
}
__device__ __forceinline__ void ldsm4(uint32_t* d, uint32_t addr) {
    asm volatile("ldmatrix.sync.aligned.m8n8.x4.shared.b16 {%0,%1,%2,%3}, [%4];"
                 : "=r"(d[0]), "=r"(d[1]), "=r"(d[2]), "=r"(d[3]) : "r"(addr));
}
__device__ __forceinline__ void mma16816(float* c, const uint32_t* a, const uint32_t* b) {
    asm volatile("mma.sync.aligned.m16n8k16.row.col.f32.f16.f16.f32 "
                 "{%0,%1,%2,%3}, {%4,%5,%6,%7}, {%8,%9}, {%0,%1,%2,%3};"
                 : "+f"(c[0]), "+f"(c[1]), "+f"(c[2]), "+f"(c[3])
                 : "r"(a[0]), "r"(a[1]), "r"(a[2]), "r"(a[3]), "r"(b[0]), "r"(b[1]));
}
__device__ __forceinline__ void red_release_add(unsigned* p, unsigned v) {
    asm volatile("red.release.gpu.global.add.u32 [%0], %1;" :: "l"(p), "r"(v) : "memory");
}
__device__ __forceinline__ unsigned ld_acquire(const unsigned* p) {
    unsigned v;
    asm volatile("ld.acquire.gpu.global.u32 %0, [%1];" : "=r"(v) : "l"(p) : "memory");
    return v;
}

// ---------------- block reduce helpers ----------------------------------------
__device__ __forceinline__ float blk_reduce_max(float v, float* sm) {
    #pragma unroll
    for (int o = 16; o; o >>= 1) v = fmaxf(v, __shfl_xor_sync(0xffffffffu, v, o));
    int w = threadIdx.x >> 5;
    if ((threadIdx.x & 31) == 0) sm[w] = v;
    __syncthreads();
    float r = sm[0];
    #pragma unroll
    for (int i = 1; i < 8; i++) r = fmaxf(r, sm[i]);
    __syncthreads();
    return r;
}
__device__ __forceinline__ float blk_reduce_sum(float v, float* sm) {
    #pragma unroll
    for (int o = 16; o; o >>= 1) v += __shfl_xor_sync(0xffffffffu, v, o);
    int w = threadIdx.x >> 5;
    if ((threadIdx.x & 31) == 0) sm[w] = v;
    __syncthreads();
    float r = sm[0];
    #pragma unroll
    for (int i = 1; i < 8; i++) r += sm[i];
    __syncthreads();
    return r;
}
struct ScanRes { float excl; float total; };
__device__ __forceinline__ ScanRes blk_scan(float s, float* sm) {
    float ws = s;
    #pragma unroll
    for (int o = 1; o < 32; o <<= 1) {
        float t = __shfl_up_sync(0xffffffffu, ws, o);
        if ((threadIdx.x & 31) >= o) ws += t;
    }
    int w = threadIdx.x >> 5;
    if ((threadIdx.x & 31) == 31) sm[w] = ws;
    __syncthreads();
    float warpBase = 0.f, run = 0.f;
    #pragma unroll
    for (int i = 0; i < 8; i++) { float t = sm[i]; if (i == w) warpBase = run; run += t; }
    __syncthreads();
    ScanRes r; r.excl = warpBase + (ws - s); r.total = run; return r;
}

// ---------------- init kernels -------------------------------------------------
__global__ void ktrans_W(const float* __restrict__ k1, const float* __restrict__ k2,
                         const float* __restrict__ k3) {
    __shared__ float tile[32][33];
    int kt = blockIdx.x * 32, nt = blockIdx.y * 32;
    int tx = threadIdx.x, ty = threadIdx.y;
    #pragma unroll
    for (int i = 0; i < 32; i += 8) {
        int k = kt + ty + i, n = nt + tx;
        const float* src; int kr;
        if (k < Dd) { src = k1; kr = k; }
        else if (k < Dd + U) { src = k2; kr = k - Dd; }
        else { src = k3; kr = k - Dd - U; }
        tile[ty + i][tx] = src[(size_t)kr * N5 + n];
    }
    __syncthreads();
    #pragma unroll
    for (int i = 0; i < 32; i += 8) {
        int n = nt + ty + i, k = kt + tx;
        g_Wt[(size_t)n * KTOT + k] = __float2half(tile[tx][ty + i]);
    }
}
__global__ void ktrans_AG(const float* __restrict__ agg) {
    __shared__ float tile[32][33];
    int kt = blockIdx.x * 32, nt = blockIdx.y * 32;
    int tx = threadIdx.x, ty = threadIdx.y;
    #pragma unroll
    for (int i = 0; i < 32; i += 8)
        tile[ty + i][tx] = agg[(size_t)(kt + ty + i) * U + nt + tx];
    __syncthreads();
    #pragma unroll
    for (int i = 0; i < 32; i += 8) {
        int n = nt + ty + i, k = kt + tx;
        g_AGt[(size_t)n * N3 + k] = __float2half(tile[tx][ty + i]);
    }
}

__global__ void kinit_scalars(const float* a0, const float* b0, const float* a1, const float* b1,
                              const float* a2, const float* b2, const float* a3, const float* b3,
                              const float* a4, const float* b4, const float* a5, const float* b5) {
    __shared__ float sm[8];
    const float* as[6] = {a0, a1, a2, a3, a4, a5};
    const float* bs[6] = {b0, b1, b2, b3, b4, b5};
    for (int p = 0; p < 6; p++) {
        float s = 0.f;
        for (int i = threadIdx.x; i < U; i += 256) s += as[p][i] * bs[p][i];
        float tot = blk_reduce_sum(s, sm);
        if (threadIdx.x == 0) g_s[p] = tot;
        __syncthreads();
    }
}

__global__ void kinit_A(const float* __restrict__ x) {
    int b = blockIdx.x;
    for (int i = threadIdx.x; i < KTOT; i += 256)
        g_A16[b * KTOT + i] = __float2half((i < Dd) ? x[(size_t)(b * T) * Dd + i] : 0.f);
    for (int i = threadIdx.x; i < U; i += 256) g_c[b * U + i] = 0.f;
    if (b == 0 && threadIdx.x < T) {
        g_zcnt[threadIdx.x] = 0u;
        g_fcnt[threadIdx.x] = 0u;
    }
}

// ---------------- generic GEMM body (device fn, exact R6 config) ---------------
template<int MODE>
__device__ __forceinline__ void gemm_body(uint32_t smb, int tid, int n0, int ks,
                                          const float* __restrict__ bias) {
    constexpr int LDK  = (MODE == 0) ? KTOT : N3;
    constexpr int NTOT = (MODE == 0) ? N5 : U;
    constexpr int KLEN = (MODE == 0) ? ZKLEN : FKLEN;
    constexpr int NC   = KLEN / KCH;

    const __half* Wp = (MODE == 0) ? g_Wt : g_AGt;
    const __half* Ap = (MODE == 0) ? g_A16 : g_O16;
    float* OUT = (MODE == 0) ? g_zp : g_fp;

    const int kbase = ks * KLEN;
    const int lane  = tid & 31;
    const int w     = tid >> 5;

    const __half* srcB[6];
    uint32_t dstO[6];
    #pragma unroll
    for (int i = 0; i < 6; i++) {
        int seg = tid + i * 256;
        if (seg < 512) {
            int r = seg >> 3, s = seg & 7;
            srcB[i] = Ap + (size_t)r * LDK + s * 8;
            dstO[i] = r * ROWB + s * 16;
        } else {
            int idx = seg - 512;
            int r = idx >> 3, s = idx & 7;
            srcB[i] = Wp + (size_t)(n0 + r) * LDK + s * 8;
            dstO[i] = A_BLK + r * ROWB + s * 16;
        }
    }
    auto load_chunk = [&](int kk, int stg) {
        const uint32_t bb = smb + stg * STG_BYTES;
        #pragma unroll
        for (int i = 0; i < 6; i++)
            cpasync16(bb + dstO[i], srcB[i] + kk);
        cp_commit();
    };

    const int mrow0 = (w & 1) * 32;
    const int nrow0 = (w >> 1) * 32;
    const int rA  = mrow0 + (lane & 15);
    const int scA = lane >> 4;
    const int rB  = nrow0 + ((lane >> 4) << 3) + (lane & 7);
    const int scB = (lane >> 3) & 1;

    float acc[2][4][4] = {};

    #pragma unroll
    for (int p = 0; p < 3; p++)
        if (p < NC) load_chunk(kbase + p * KCH, p);

    for (int c = 0; c < NC; c++) {
        int rem = NC - 1 - c;
        if (rem >= 2) cp_wait<2>(); else if (rem == 1) cp_wait<1>(); else cp_wait<0>();
        __syncthreads();
        if (c + 3 < NC) load_chunk(kbase + (c + 3) * KCH, (c + 3) % NSTG);

        const uint32_t bb = smb + (c % NSTG) * STG_BYTES;
        #pragma unroll
        for (int s16 = 0; s16 < 4; s16++) {
            const int kd = s16 * 2;
            uint32_t ah[2][4], bh[2][4];
            #pragma unroll
            for (int mi = 0; mi < 2; mi++)
                ldsm4(ah[mi], bb + (rA + mi * 16) * ROWB + (kd + scA) * 16);
            #pragma unroll
            for (int nj = 0; nj < 2; nj++)
                ldsm4(bh[nj], bb + A_BLK + (rB + nj * 16) * ROWB + (kd + scB) * 16);
            #pragma unroll
            for (int mi = 0; mi < 2; mi++)
                #pragma unroll
                for (int nf = 0; nf < 4; nf++)
                    mma16816(acc[mi][nf], ah[mi], &bh[nf >> 1][(nf & 1) * 2]);
        }
    }

    #pragma unroll
    for (int mi = 0; mi < 2; mi++) {
        #pragma unroll
        for (int nf = 0; nf < 4; nf++) {
            int row = mrow0 + mi * 16 + (lane >> 2);
            int col = n0 + nrow0 + nf * 8 + (lane & 3) * 2;
            float2 v0 = make_float2(acc[mi][nf][0], acc[mi][nf][1]);
            float2 v1 = make_float2(acc[mi][nf][2], acc[mi][nf][3]);
            if (MODE == 0 && ks == 0) {
                v0.x += bias[col]; v0.y += bias[col + 1];
                v1.x += bias[col]; v1.y += bias[col + 1];
            }
            *reinterpret_cast<float2*>(OUT + (size_t)(ks * Bsz + row) * NTOT + col) = v0;
            *reinterpret_cast<float2*>(OUT + (size_t)(ks * Bsz + row + 8) * NTOT + col) = v1;
        }
    }
}

// ---------------- gate body (device fn) ----------------------------------------
__device__ __forceinline__ void gate_body(int b, int tid) {
    __shared__ float sm[16];
    const int i0 = tid * 4;

    float uz[4], dz[4], rz[4];
    {
        #define LOAD3(off, out) {                                                   \
            float4 s0 = *reinterpret_cast<const float4*>(g_zp + (size_t)(0*Bsz+b)*N5 + (off)); \
            float4 s1 = *reinterpret_cast<const float4*>(g_zp + (size_t)(1*Bsz+b)*N5 + (off)); \
            float4 s2 = *reinterpret_cast<const float4*>(g_zp + (size_t)(2*Bsz+b)*N5 + (off)); \
            out[0] = s0.x + s1.x + s2.x; out[1] = s0.y + s1.y + s2.y;                  \
            out[2] = s0.z + s1.z + s2.z; out[3] = s0.w + s1.w + s2.w; }
        LOAD3(i0,         uz)
        LOAD3(U + i0,     dz)
        LOAD3(2 * U + i0, rz)
        #undef LOAD3
    }

    float mx = fmaxf(fmaxf(uz[0], uz[1]), fmaxf(uz[2], uz[3]));
    mx = blk_reduce_max(mx, sm);
    float e[4], ls = 0.f;
    #pragma unroll
    for (int l = 0; l < 4; l++) { e[l] = expf(uz[l] - mx); ls += e[l]; }
    ScanRes s1 = blk_scan(ls, sm);
    float up[4];
    { float P = s1.excl, inv = 1.f / s1.total;
      #pragma unroll
      for (int l = 0; l < 4; l++) { P += e[l]; up[l] = P * inv; } }

    float mx2 = fmaxf(fmaxf(dz[0], dz[1]), fmaxf(dz[2], dz[3]));
    mx2 = blk_reduce_max(mx2, sm);
    float ed[4]; ls = 0.f;
    #pragma unroll
    for (int l = 0; l < 4; l++) { ed[l] = expf(dz[l] - mx2); ls += ed[l]; }
    ScanRes s2 = blk_scan(ls, sm);
    float dn[4];
    { float P = s2.excl, inv = 1.f / s2.total;
      #pragma unroll
      for (int l = 0; l < 4; l++) { P += ed[l]; dn[l] = (s2.total - P + ed[l]) * inv; } }

    float pdu = 0.f, pru = 0.f, pdr = 0.f;
    #pragma unroll
    for (int l = 0; l < 4; l++) { pdu += dn[l] * up[l]; pru += rz[l] * up[l]; pdr += dn[l] * rz[l]; }
    float du = blk_reduce_sum(pdu, sm);
    float ru = blk_reduce_sum(pru, sm);
    float dr = blk_reduce_sum(pdr, sm);

    const float s_ud = g_s[0], s_ur = g_s[1], s_ru = g_s[2];
    const float s_rd = g_s[3], s_du = g_s[4], s_dr = g_s[5];

    #pragma unroll
    for (int l = 0; l < 4; l++) {
        float t1 = sigf(s_ud * up[l] * du) + sigf(s_ur * up[l] * ru);
        float t2 = sigf(s_ru * rz[l] * ru) + sigf(s_rd * rz[l] * dr);
        float t3 = sigf(s_du * dn[l] * du) + sigf(s_dr * dn[l] * dr);
        g_O16[b * N3 + i0 + l]         = __float2half(t1);
        g_O16[b * N3 + U + i0 + l]     = __float2half(t2);
        g_O16[b * N3 + 2 * U + i0 + l] = __float2half(t3);
    }
}

// ---------------- update body (device fn) --------------------------------------
__device__ __forceinline__ void update_body(int b, int tid, int t,
                                            const float* __restrict__ x,
                                            float* __restrict__ out) {
    const int j0 = tid * 4;
    #pragma unroll
    for (int l = 0; l < 4; l++) {
        int j = j0 + l;
        float fs = 0.f;
        #pragma unroll
        for (int ks = 0; ks < FSPLIT; ks++) fs += g_fp[(size_t)(ks * Bsz + b) * U + j];
        float f = sigf(fs);
        float og = 0.f, zc = 0.f;
        #pragma unroll
        for (int ks = 0; ks < ZSPLIT; ks++) {
            og += g_zp[(size_t)(ks * Bsz + b) * N5 + 3 * U + j];
            zc += g_zp[(size_t)(ks * Bsz + b) * N5 + 4 * U + j];
        }
        float ci = tanhf(zc);
        float co = g_c[b * U + j];
        float cn = f * co + (1.f - f) * ci;
        float hn = og * tanhf(cn);
        g_c[b * U + j] = cn;
        out[((size_t)b * T + t) * U + j] = hn;
        g_A16[b * KTOT + Dd + j]     = __float2half(hn);
        g_A16[b * KTOT + Dd + U + j] = __float2half(cn);
    }
    if (t + 1 < T && tid < 64) {
        #pragma unroll
        for (int l = 0; l < 4; l++) {
            int d = tid * 4 + l;
            g_A16[b * KTOT + d] = __float2half(x[((size_t)b * T + (t + 1)) * Dd + d]);
        }
    }
}

// ---------------- kernel 1: z-GEMM producers + gate consumers -------------------
__global__ void __launch_bounds__(256) k_zg(const float* __restrict__ bias, int t) {
    const int bid = blockIdx.x, tid = threadIdx.x;
    extern __shared__ char dyn[];
    if (bid < ZCTAS) {
        gemm_body<0>(smem_u32(dyn), tid, (bid % 40) * NTILE, bid / 40, bias);
        __syncthreads();
        if (tid == 0) red_release_add(&g_zcnt[t], 1u);
    } else {
        if (tid == 0) {
            while (ld_acquire(&g_zcnt[t]) < (unsigned)ZCTAS) __nanosleep(32);
        }
        __syncthreads();
        gate_body(bid - ZCTAS, tid);
    }
}

// ---------------- kernel 2: agg-GEMM producers + update consumers ---------------
__global__ void __launch_bounds__(256) k_fu(const float* __restrict__ x,
                                            float* __restrict__ out, int t) {
    const int bid = blockIdx.x, tid = threadIdx.x;
    extern __shared__ char dyn[];
    if (bid < FCTAS) {
        gemm_body<1>(smem_u32(dyn), tid, (bid % 8) * NTILE, bid / 8, nullptr);
        __syncthreads();
        if (tid == 0) red_release_add(&g_fcnt[t], 1u);
    } else {
        if (tid == 0) {
            while (ld_acquire(&g_fcnt[t]) < (unsigned)FCTAS) __nanosleep(32);
        }
        __syncthreads();
        update_body(bid - FCTAS, tid, t, x, out);
    }
}

// ---------------- launch ---------------------------------------------------------
extern "C" void kernel_launch(void* const* d_in, const int* in_sizes, int n_in,
                              void* d_out, int out_size) {
    const float* x    = (const float*)d_in[0];
    const float* kern = (const float*)d_in[1];
    const float* rker = (const float*)d_in[2];
    const float* cker = (const float*)d_in[3];
    const float* bias = (const float*)d_in[4];
    const float* agg  = (const float*)d_in[5];
    float* out = (float*)d_out;

    cudaFuncSetAttribute(k_zg, cudaFuncAttributeMaxDynamicSharedMemorySize, GSMEM_BYTES);
    cudaFuncSetAttribute(k_fu, cudaFuncAttributeMaxDynamicSharedMemorySize, GSMEM_BYTES);

    ktrans_W <<<dim3(KTOT / 32, N5 / 32), dim3(32, 8)>>>(kern, rker, cker);
    ktrans_AG<<<dim3(N3 / 32,  U  / 32), dim3(32, 8)>>>(agg);
    kinit_scalars<<<1, 256>>>((const float*)d_in[6],  (const float*)d_in[7],
                              (const float*)d_in[8],  (const float*)d_in[9],
                              (const float*)d_in[10], (const float*)d_in[11],
                              (const float*)d_in[12], (const float*)d_in[13],
                              (const float*)d_in[14], (const float*)d_in[15],
                              (const float*)d_in[16], (const float*)d_in[17]);
    kinit_A<<<Bsz, 256>>>(x);

    for (int t = 0; t < T; t++) {
        k_zg<<<ZCTAS + Bsz, 256, GSMEM_BYTES>>>(bias, t);
        k_fu<<<FCTAS + Bsz, 256, GSMEM_BYTES>>>(x, out, t);
    }
}

// round 12
// speedup vs baseline: 2.2576x; 1.0499x over previous
#include <cuda_runtime.h>
#include <cuda_fp16.h>
#include <math.h>
#include <stdint.h>

#define U   1024
#define Bsz 64
#define T   128
#define Dd  256
#define N5  (5*U)        // 5120
#define N3  (3*U)        // 3072
#define KTOT (Dd + 2*U)  // 2304

#define NCTA   120                     // co-resident grid (<=148, 1 CTA/SM)
#define ZSPLIT 3
#define ZKLEN  (KTOT / ZSPLIT)   // 768
#define FSPLIT 12
#define FKLEN  (N3 / FSPLIT)     // 256
#define FCTAS  (U / 128 * FSPLIT)      // 96
#define NTILE  128
#define KCH    64                // K elems per chunk (128 B rows fp16)

// SMEM: rows padded to 144B -> conflict-free ldmatrix
#define ROWB   144
#define A_BLK  (64 * ROWB)             // 9216
#define B_BLK  (128 * ROWB)            // 18432
#define STG_BYTES (A_BLK + B_BLK)      // 27648
#define NSTG   4
#define GSMEM_BYTES (NSTG * STG_BYTES) // 110592

// ---------------- static device scratch --------------------------------------
__device__ __align__(128) __half g_Wt [(size_t)N5 * KTOT];  // W^T fp16 [n][k]
__device__ __align__(128) __half g_AGt[(size_t)U * N3];     // agg^T fp16 [n][k]
__device__ __align__(128) __half g_A16[Bsz * KTOT];         // [x|h|c] fp16
__device__ __align__(128) __half g_O16[Bsz * N3];           // O fp16
__device__ __align__(128) float g_c  [Bsz * U];
__device__ __align__(128) float g_zp [ZSPLIT * Bsz * N5];
__device__ __align__(128) float g_fp [FSPLIT * Bsz * U];
__device__ float g_s[6];
__device__ unsigned g_barA[T];
__device__ unsigned g_barB[T];
__device__ unsigned g_barC[T];

// ---------------- helpers -----------------------------------------------------
__device__ __forceinline__ float sigf(float x) { return 1.f / (1.f + expf(-x)); }

__device__ __forceinline__ uint32_t smem_u32(const void* p) {
    uint32_t a;
    asm("{ .reg .u64 t; cvta.to.shared.u64 t, %1; cvt.u32.u64 %0, t; }" : "=r"(a) : "l"(p));
    return a;
}
__device__ __forceinline__ void cpasync16(uint32_t s, const void* g) {
    asm volatile("cp.async.cg.shared.global [%0], [%1], 16;" :: "r"(s), "l"(g) : "memory");
}
__device__ __forceinline__ void cp_commit() { asm volatile("cp.async.commit_group;" ::: "memory"); }
template<int N> __device__ __forceinline__ void cp_wait() {
    asm volatile("cp.async.wait_group %0;" :: "n"(N) : "memory");
}
__device__ __forceinline__ void ldsm4(uint32_t* d, uint32_t addr) {
    asm volatile("ldmatrix.sync.aligned.m8n8.x4.shared.b16 {%0,%1,%2,%3}, [%4];"
                 : "=r"(d[0]), "=r"(d[1]), "=r"(d[2]), "=r"(d[3]) : "r"(addr));
}
__device__ __forceinline__ void mma16816(float* c, const uint32_t* a, const uint32_t* b) {
    asm volatile("mma.sync.aligned.m16n8k16.row.col.f32.f16.f16.f32 "
                 "{%0,%1,%2,%3}, {%4,%5,%6,%7}, {%8,%9}, {%0,%1,%2,%3};"
                 : "+f"(c[0]), "+f"(c[1]), "+f"(c[2]), "+f"(c[3])
                 : "r"(a[0]), "r"(a[1]), "r"(a[2]), "r"(a[3]), "r"(b[0]), "r"(b[1]));
}
__device__ __forceinline__ void red_release_add(unsigned* p, unsigned v) {
    asm volatile("red.release.gpu.global.add.u32 [%0], %1;" :: "l"(p), "r"(v) : "memory");
}
__device__ __forceinline__ unsigned ld_acquire(const unsigned* p) {
    unsigned v;
    asm volatile("ld.acquire.gpu.global.u32 %0, [%1];" : "=r"(v) : "l"(p) : "memory");
    return v;
}
// grid-wide barrier among the NCTA co-resident CTAs
__device__ __forceinline__ void gbar(unsigned* ctr, int tid) {
    __syncthreads();
    if (tid == 0) {
        red_release_add(ctr, 1u);
        while (ld_acquire(ctr) < (unsigned)NCTA) __nanosleep(32);
    }
    __syncthreads();
}

// ---------------- block reduce helpers ----------------------------------------
__device__ __forceinline__ float blk_reduce_max(float v, float* sm) {
    #pragma unroll
    for (int o = 16; o; o >>= 1) v = fmaxf(v, __shfl_xor_sync(0xffffffffu, v, o));
    int w = threadIdx.x >> 5;
    if ((threadIdx.x & 31) == 0) sm[w] = v;
    __syncthreads();
    float r = sm[0];
    #pragma unroll
    for (int i = 1; i < 8; i++) r = fmaxf(r, sm[i]);
    __syncthreads();
    return r;
}
__device__ __forceinline__ float blk_reduce_sum(float v, float* sm) {
    #pragma unroll
    for (int o = 16; o; o >>= 1) v += __shfl_xor_sync(0xffffffffu, v, o);
    int w = threadIdx.x >> 5;
    if ((threadIdx.x & 31) == 0) sm[w] = v;
    __syncthreads();
    float r = sm[0];
    #pragma unroll
    for (int i = 1; i < 8; i++) r += sm[i];
    __syncthreads();
    return r;
}
struct ScanRes { float excl; float total; };
__device__ __forceinline__ ScanRes blk_scan(float s, float* sm) {
    float ws = s;
    #pragma unroll
    for (int o = 1; o < 32; o <<= 1) {
        float t = __shfl_up_sync(0xffffffffu, ws, o);
        if ((threadIdx.x & 31) >= o) ws += t;
    }
    int w = threadIdx.x >> 5;
    if ((threadIdx.x & 31) == 31) sm[w] = ws;
    __syncthreads();
    float warpBase = 0.f, run = 0.f;
    #pragma unroll
    for (int i = 0; i < 8; i++) { float t = sm[i]; if (i == w) warpBase = run; run += t; }
    __syncthreads();
    ScanRes r; r.excl = warpBase + (ws - s); r.total = run; return r;
}

// ---------------- init kernels -------------------------------------------------
__global__ void ktrans_W(const float* __restrict__ k1, const float* __restrict__ k2,
                         const float* __restrict__ k3) {
    __shared__ float tile[32][33];
    int kt = blockIdx.x * 32, nt = blockIdx.y * 32;
    int tx = threadIdx.x, ty = threadIdx.y;
    #pragma unroll
    for (int i = 0; i < 32; i += 8) {
        int k = kt + ty + i, n = nt + tx;
        const float* src; int kr;
        if (k < Dd) { src = k1; kr = k; }
        else if (k < Dd + U) { src = k2; kr = k - Dd; }
        else { src = k3; kr = k - Dd - U; }
        tile[ty + i][tx] = src[(size_t)kr * N5 + n];
    }
    __syncthreads();
    #pragma unroll
    for (int i = 0; i < 32; i += 8) {
        int n = nt + ty + i, k = kt + tx;
        g_Wt[(size_t)n * KTOT + k] = __float2half(tile[tx][ty + i]);
    }
}
__global__ void ktrans_AG(const float* __restrict__ agg) {
    __shared__ float tile[32][33];
    int kt = blockIdx.x * 32, nt = blockIdx.y * 32;
    int tx = threadIdx.x, ty = threadIdx.y;
    #pragma unroll
    for (int i = 0; i < 32; i += 8)
        tile[ty + i][tx] = agg[(size_t)(kt + ty + i) * U + nt + tx];
    __syncthreads();
    #pragma unroll
    for (int i = 0; i < 32; i += 8) {
        int n = nt + ty + i, k = kt + tx;
        g_AGt[(size_t)n * N3 + k] = __float2half(tile[tx][ty + i]);
    }
}

__global__ void kinit_scalars(const float* a0, const float* b0, const float* a1, const float* b1,
                              const float* a2, const float* b2, const float* a3, const float* b3,
                              const float* a4, const float* b4, const float* a5, const float* b5) {
    __shared__ float sm[8];
    const float* as[6] = {a0, a1, a2, a3, a4, a5};
    const float* bs[6] = {b0, b1, b2, b3, b4, b5};
    for (int p = 0; p < 6; p++) {
        float s = 0.f;
        for (int i = threadIdx.x; i < U; i += 256) s += as[p][i] * bs[p][i];
        float tot = blk_reduce_sum(s, sm);
        if (threadIdx.x == 0) g_s[p] = tot;
        __syncthreads();
    }
}

__global__ void kinit_A(const float* __restrict__ x) {
    int b = blockIdx.x;
    for (int i = threadIdx.x; i < KTOT; i += 256)
        g_A16[b * KTOT + i] = __float2half((i < Dd) ? x[(size_t)(b * T) * Dd + i] : 0.f);
    for (int i = threadIdx.x; i < U; i += 256) g_c[b * U + i] = 0.f;
    if (b == 0 && threadIdx.x < T) {
        g_barA[threadIdx.x] = 0u;
        g_barB[threadIdx.x] = 0u;
        g_barC[threadIdx.x] = 0u;
    }
}

// ---------------- generic GEMM body (device fn, exact R9 config) ---------------
template<int MODE>
__device__ __forceinline__ void gemm_body(uint32_t smb, int tid, int n0, int ks,
                                          const float* __restrict__ bias) {
    constexpr int LDK  = (MODE == 0) ? KTOT : N3;
    constexpr int NTOT = (MODE == 0) ? N5 : U;
    constexpr int KLEN = (MODE == 0) ? ZKLEN : FKLEN;
    constexpr int NC   = KLEN / KCH;

    const __half* Wp = (MODE == 0) ? g_Wt : g_AGt;
    const __half* Ap = (MODE == 0) ? g_A16 : g_O16;
    float* OUT = (MODE == 0) ? g_zp : g_fp;

    const int kbase = ks * KLEN;
    const int lane  = tid & 31;
    const int w     = tid >> 5;

    const __half* srcB[6];
    uint32_t dstO[6];
    #pragma unroll
    for (int i = 0; i < 6; i++) {
        int seg = tid + i * 256;
        if (seg < 512) {
            int r = seg >> 3, s = seg & 7;
            srcB[i] = Ap + (size_t)r * LDK + s * 8;
            dstO[i] = r * ROWB + s * 16;
        } else {
            int idx = seg - 512;
            int r = idx >> 3, s = idx & 7;
            srcB[i] = Wp + (size_t)(n0 + r) * LDK + s * 8;
            dstO[i] = A_BLK + r * ROWB + s * 16;
        }
    }
    auto load_chunk = [&](int kk, int stg) {
        const uint32_t bb = smb + stg * STG_BYTES;
        #pragma unroll
        for (int i = 0; i < 6; i++)
            cpasync16(bb + dstO[i], srcB[i] + kk);
        cp_commit();
    };

    const int mrow0 = (w & 1) * 32;
    const int nrow0 = (w >> 1) * 32;
    const int rA  = mrow0 + (lane & 15);
    const int scA = lane >> 4;
    const int rB  = nrow0 + ((lane >> 4) << 3) + (lane & 7);
    const int scB = (lane >> 3) & 1;

    float acc[2][4][4] = {};

    #pragma unroll
    for (int p = 0; p < 3; p++)
        if (p < NC) load_chunk(kbase + p * KCH, p);

    for (int c = 0; c < NC; c++) {
        int rem = NC - 1 - c;
        if (rem >= 2) cp_wait<2>(); else if (rem == 1) cp_wait<1>(); else cp_wait<0>();
        __syncthreads();
        if (c + 3 < NC) load_chunk(kbase + (c + 3) * KCH, (c + 3) % NSTG);

        const uint32_t bb = smb + (c % NSTG) * STG_BYTES;
        #pragma unroll
        for (int s16 = 0; s16 < 4; s16++) {
            const int kd = s16 * 2;
            uint32_t ah[2][4], bh[2][4];
            #pragma unroll
            for (int mi = 0; mi < 2; mi++)
                ldsm4(ah[mi], bb + (rA + mi * 16) * ROWB + (kd + scA) * 16);
            #pragma unroll
            for (int nj = 0; nj < 2; nj++)
                ldsm4(bh[nj], bb + A_BLK + (rB + nj * 16) * ROWB + (kd + scB) * 16);
            #pragma unroll
            for (int mi = 0; mi < 2; mi++)
                #pragma unroll
                for (int nf = 0; nf < 4; nf++)
                    mma16816(acc[mi][nf], ah[mi], &bh[nf >> 1][(nf & 1) * 2]);
        }
    }

    #pragma unroll
    for (int mi = 0; mi < 2; mi++) {
        #pragma unroll
        for (int nf = 0; nf < 4; nf++) {
            int row = mrow0 + mi * 16 + (lane >> 2);
            int col = n0 + nrow0 + nf * 8 + (lane & 3) * 2;
            float2 v0 = make_float2(acc[mi][nf][0], acc[mi][nf][1]);
            float2 v1 = make_float2(acc[mi][nf][2], acc[mi][nf][3]);
            if (MODE == 0 && ks == 0) {
                v0.x += bias[col]; v0.y += bias[col + 1];
                v1.x += bias[col]; v1.y += bias[col + 1];
            }
            *reinterpret_cast<float2*>(OUT + (size_t)(ks * Bsz + row) * NTOT + col) = v0;
            *reinterpret_cast<float2*>(OUT + (size_t)(ks * Bsz + row + 8) * NTOT + col) = v1;
        }
    }
}

// ---------------- gate body (device fn) ----------------------------------------
__device__ __forceinline__ void gate_body(int b, int tid) {
    __shared__ float sm[16];
    const int i0 = tid * 4;

    float uz[4], dz[4], rz[4];
    {
        #define LOAD3(off, out) {                                                   \
            float4 s0 = *reinterpret_cast<const float4*>(g_zp + (size_t)(0*Bsz+b)*N5 + (off)); \
            float4 s1 = *reinterpret_cast<const float4*>(g_zp + (size_t)(1*Bsz+b)*N5 + (off)); \
            float4 s2 = *reinterpret_cast<const float4*>(g_zp + (size_t)(2*Bsz+b)*N5 + (off)); \
            out[0] = s0.x + s1.x + s2.x; out[1] = s0.y + s1.y + s2.y;                  \
            out[2] = s0.z + s1.z + s2.z; out[3] = s0.w + s1.w + s2.w; }
        LOAD3(i0,         uz)
        LOAD3(U + i0,     dz)
        LOAD3(2 * U + i0, rz)
        #undef LOAD3
    }

    float mx = fmaxf(fmaxf(uz[0], uz[1]), fmaxf(uz[2], uz[3]));
    mx = blk_reduce_max(mx, sm);
    float e[4], ls = 0.f;
    #pragma unroll
    for (int l = 0; l < 4; l++) { e[l] = expf(uz[l] - mx); ls += e[l]; }
    ScanRes s1 = blk_scan(ls, sm);
    float up[4];
    { float P = s1.excl, inv = 1.f / s1.total;
      #pragma unroll
      for (int l = 0; l < 4; l++) { P += e[l]; up[l] = P * inv; } }

    float mx2 = fmaxf(fmaxf(dz[0], dz[1]), fmaxf(dz[2], dz[3]));
    mx2 = blk_reduce_max(mx2, sm);
    float ed[4]; ls = 0.f;
    #pragma unroll
    for (int l = 0; l < 4; l++) { ed[l] = expf(dz[l] - mx2); ls += ed[l]; }
    ScanRes s2 = blk_scan(ls, sm);
    float dn[4];
    { float P = s2.excl, inv = 1.f / s2.total;
      #pragma unroll
      for (int l = 0; l < 4; l++) { P += ed[l]; dn[l] = (s2.total - P + ed[l]) * inv; } }

    float pdu = 0.f, pru = 0.f, pdr = 0.f;
    #pragma unroll
    for (int l = 0; l < 4; l++) { pdu += dn[l] * up[l]; pru += rz[l] * up[l]; pdr += dn[l] * rz[l]; }
    float du = blk_reduce_sum(pdu, sm);
    float ru = blk_reduce_sum(pru, sm);
    float dr = blk_reduce_sum(pdr, sm);

    const float s_ud = g_s[0], s_ur = g_s[1], s_ru = g_s[2];
    const float s_rd = g_s[3], s_du = g_s[4], s_dr = g_s[5];

    #pragma unroll
    for (int l = 0; l < 4; l++) {
        float t1 = sigf(s_ud * up[l] * du) + sigf(s_ur * up[l] * ru);
        float t2 = sigf(s_ru * rz[l] * ru) + sigf(s_rd * rz[l] * dr);
        float t3 = sigf(s_du * dn[l] * du) + sigf(s_dr * dn[l] * dr);
        g_O16[b * N3 + i0 + l]         = __float2half(t1);
        g_O16[b * N3 + U + i0 + l]     = __float2half(t2);
        g_O16[b * N3 + 2 * U + i0 + l] = __float2half(t3);
    }
}

// ---------------- update body (device fn) --------------------------------------
__device__ __forceinline__ void update_body(int b, int tid, int t,
                                            const float* __restrict__ x,
                                            float* __restrict__ out) {
    const int j0 = tid * 4;
    #pragma unroll
    for (int l = 0; l < 4; l++) {
        int j = j0 + l;
        float fs = 0.f;
        #pragma unroll
        for (int ks = 0; ks < FSPLIT; ks++) fs += g_fp[(size_t)(ks * Bsz + b) * U + j];
        float f = sigf(fs);
        float og = 0.f, zc = 0.f;
        #pragma unroll
        for (int ks = 0; ks < ZSPLIT; ks++) {
            og += g_zp[(size_t)(ks * Bsz + b) * N5 + 3 * U + j];
            zc += g_zp[(size_t)(ks * Bsz + b) * N5 + 4 * U + j];
        }
        float ci = tanhf(zc);
        float co = g_c[b * U + j];
        float cn = f * co + (1.f - f) * ci;
        float hn = og * tanhf(cn);
        g_c[b * U + j] = cn;
        out[((size_t)b * T + t) * U + j] = hn;
        g_A16[b * KTOT + Dd + j]     = __float2half(hn);
        g_A16[b * KTOT + Dd + U + j] = __float2half(cn);
    }
    if (t + 1 < T && tid < 64) {
        #pragma unroll
        for (int l = 0; l < 4; l++) {
            int d = tid * 4 + l;
            g_A16[b * KTOT + d] = __float2half(x[((size_t)b * T + (t + 1)) * Dd + d]);
        }
    }
}

// ---------------- single per-step kernel: 120 co-resident CTAs, 4 phases --------
__global__ void __launch_bounds__(256) k_step(const float* __restrict__ bias,
                                              const float* __restrict__ x,
                                              float* __restrict__ out, int t) {
    const int bid = blockIdx.x, tid = threadIdx.x;
    extern __shared__ char dyn[];
    const uint32_t smb = smem_u32(dyn);

    // phase 1: z-GEMM on all 120 CTAs
    gemm_body<0>(smb, tid, (bid % 40) * NTILE, bid / 40, bias);
    gbar(&g_barA[t], tid);

    // phase 2: gates on CTAs 0..63
    if (bid < Bsz) gate_body(bid, tid);
    gbar(&g_barB[t], tid);

    // phase 3: agg-GEMM on CTAs 0..95 (8 N-tiles x FSPLIT=12)
    if (bid < FCTAS) gemm_body<1>(smb, tid, (bid % 8) * NTILE, bid / 8, nullptr);
    gbar(&g_barC[t], tid);

    // phase 4: update on CTAs 0..63
    if (bid < Bsz) update_body(bid, tid, t, x, out);
}

// ---------------- launch ---------------------------------------------------------
extern "C" void kernel_launch(void* const* d_in, const int* in_sizes, int n_in,
                              void* d_out, int out_size) {
    const float* x    = (const float*)d_in[0];
    const float* kern = (const float*)d_in[1];
    const float* rker = (const float*)d_in[2];
    const float* cker = (const float*)d_in[3];
    const float* bias = (const float*)d_in[4];
    const float* agg  = (const float*)d_in[5];
    float* out = (float*)d_out;

    cudaFuncSetAttribute(k_step, cudaFuncAttributeMaxDynamicSharedMemorySize, GSMEM_BYTES);

    ktrans_W <<<dim3(KTOT / 32, N5 / 32), dim3(32, 8)>>>(kern, rker, cker);
    ktrans_AG<<<dim3(N3 / 32,  U  / 32), dim3(32, 8)>>>(agg);
    kinit_scalars<<<1, 256>>>((const float*)d_in[6],  (const float*)d_in[7],
                              (const float*)d_in[8],  (const float*)d_in[9],
                              (const float*)d_in[10], (const float*)d_in[11],
                              (const float*)d_in[12], (const float*)d_in[13],
                              (const float*)d_in[14], (const float*)d_in[15],
                              (const float*)d_in[16], (const float*)d_in[17]);
    kinit_A<<<Bsz, 256>>>(x);

    for (int t = 0; t < T; t++)
        k_step<<<NCTA, 256, GSMEM_BYTES>>>(bias, x, out, t);
}

// round 13
// speedup vs baseline: 2.3757x; 1.0523x over previous
#include <cuda_runtime.h>
#include <cuda_fp16.h>
#include <math.h>
#include <stdint.h>

#define U   1024
#define Bsz 64
#define T   128
#define Dd  256
#define N5  (5*U)        // 5120
#define N3  (3*U)        // 3072
#define KTOT (Dd + 2*U)  // 2304

#define NCTA   120                     // co-resident grid (<=148 SMs, 1 CTA/SM)
#define ZSPLIT 3
#define ZKLEN  (KTOT / ZSPLIT)   // 768
#define FSPLIT 12
#define FKLEN  (N3 / FSPLIT)     // 256
#define FCTAS  (U / 128 * FSPLIT)      // 96
#define NTILE  128
#define KCH    64                // K elems per chunk (128 B rows fp16)

// SMEM: rows padded to 144B -> conflict-free ldmatrix
#define ROWB   144
#define A_BLK  (64 * ROWB)             // 9216
#define B_BLK  (128 * ROWB)            // 18432
#define STG_BYTES (A_BLK + B_BLK)      // 27648
#define NSTG   4
#define GSMEM_BYTES (NSTG * STG_BYTES) // 110592

// ---------------- static device scratch --------------------------------------
__device__ __align__(128) __half g_Wt [(size_t)N5 * KTOT];  // W^T fp16 [n][k]
__device__ __align__(128) __half g_AGt[(size_t)U * N3];     // agg^T fp16 [n][k]
__device__ __align__(128) __half g_A16[Bsz * KTOT];         // [x|h|c] fp16
__device__ __align__(128) __half g_O16[Bsz * N3];           // O fp16
__device__ __align__(128) float g_c  [Bsz * U];
__device__ __align__(128) float g_zp [ZSPLIT * Bsz * N5];
__device__ __align__(128) float g_fp [FSPLIT * Bsz * U];
__device__ float g_s[6];
__device__ unsigned g_barA[T];
__device__ unsigned g_barB[T];
__device__ unsigned g_barC[T];
__device__ unsigned g_barD[T];

// ---------------- helpers -----------------------------------------------------
__device__ __forceinline__ float sigf(float x) { return 1.f / (1.f + expf(-x)); }

__device__ __forceinline__ uint32_t smem_u32(const void* p) {
    uint32_t a;
    asm("{ .reg .u64 t; cvta.to.shared.u64 t, %1; cvt.u32.u64 %0, t; }" : "=r"(a) : "l"(p));
    return a;
}
__device__ __forceinline__ void cpasync16(uint32_t s, const void* g) {
    asm volatile("cp.async.cg.shared.global [%0], [%1], 16;" :: "r"(s), "l"(g) : "memory");
}
__device__ __forceinline__ void cp_commit() { asm volatile("cp.async.commit_group;" ::: "memory"); }
template<int N> __device__ __forceinline__ void cp_wait() {
    asm volatile("cp.async.wait_group %0;" :: "n"(N) : "memory");
}
__device__ __forceinline__ void ldsm4(uint32_t* d, uint32_t addr) {
    asm volatile("ldmatrix.sync.aligned.m8n8.x4.shared.b16 {%0,%1,%2,%3}, [%4];"
                 : "=r"(d[0]), "=r"(d[1]), "=r"(d[2]), "=r"(d[3]) : "r"(addr));
}
__device__ __forceinline__ void mma16816(float* c, const uint32_t* a, const uint32_t* b) {
    asm volatile("mma.sync.aligned.m16n8k16.row.col.f32.f16.f16.f32 "
                 "{%0,%1,%2,%3}, {%4,%5,%6,%7}, {%8,%9}, {%0,%1,%2,%3};"
                 : "+f"(c[0]), "+f"(c[1]), "+f"(c[2]), "+f"(c[3])
                 : "r"(a[0]), "r"(a[1]), "r"(a[2]), "r"(a[3]), "r"(b[0]), "r"(b[1]));
}
__device__ __forceinline__ void red_release_add(unsigned* p, unsigned v) {
    asm volatile("red.release.gpu.global.add.u32 [%0], %1;" :: "l"(p), "r"(v) : "memory");
}
__device__ __forceinline__ unsigned ld_acquire(const unsigned* p) {
    unsigned v;
    asm volatile("ld.acquire.gpu.global.u32 %0, [%1];" : "=r"(v) : "l"(p) : "memory");
    return v;
}
// L2-only loads (avoid stale L1 across persistent steps)
__device__ __forceinline__ float4 ldcg4(const float* p) {
    float4 v;
    asm volatile("ld.global.cg.v4.f32 {%0,%1,%2,%3}, [%4];"
                 : "=f"(v.x), "=f"(v.y), "=f"(v.z), "=f"(v.w) : "l"(p));
    return v;
}
// barrier among `target` participating CTAs (tid0 spin + block syncs)
__device__ __forceinline__ void gbarN(unsigned* ctr, int tid, unsigned target) {
    __syncthreads();
    if (tid == 0) {
        red_release_add(ctr, 1u);
        while (ld_acquire(ctr) < target) __nanosleep(32);
    }
    __syncthreads();
}

// ---------------- block reduce helpers ----------------------------------------
__device__ __forceinline__ float blk_reduce_max(float v, float* sm) {
    #pragma unroll
    for (int o = 16; o; o >>= 1) v = fmaxf(v, __shfl_xor_sync(0xffffffffu, v, o));
    int w = threadIdx.x >> 5;
    if ((threadIdx.x & 31) == 0) sm[w] = v;
    __syncthreads();
    float r = sm[0];
    #pragma unroll
    for (int i = 1; i < 8; i++) r = fmaxf(r, sm[i]);
    __syncthreads();
    return r;
}
__device__ __forceinline__ float blk_reduce_sum(float v, float* sm) {
    #pragma unroll
    for (int o = 16; o; o >>= 1) v += __shfl_xor_sync(0xffffffffu, v, o);
    int w = threadIdx.x >> 5;
    if ((threadIdx.x & 31) == 0) sm[w] = v;
    __syncthreads();
    float r = sm[0];
    #pragma unroll
    for (int i = 1; i < 8; i++) r += sm[i];
    __syncthreads();
    return r;
}
struct ScanRes { float excl; float total; };
__device__ __forceinline__ ScanRes blk_scan(float s, float* sm) {
    float ws = s;
    #pragma unroll
    for (int o = 1; o < 32; o <<= 1) {
        float t = __shfl_up_sync(0xffffffffu, ws, o);
        if ((threadIdx.x & 31) >= o) ws += t;
    }
    int w = threadIdx.x >> 5;
    if ((threadIdx.x & 31) == 31) sm[w] = ws;
    __syncthreads();
    float warpBase = 0.f, run = 0.f;
    #pragma unroll
    for (int i = 0; i < 8; i++) { float t = sm[i]; if (i == w) warpBase = run; run += t; }
    __syncthreads();
    ScanRes r; r.excl = warpBase + (ws - s); r.total = run; return r;
}

// ---------------- init kernels -------------------------------------------------
__global__ void ktrans_W(const float* __restrict__ k1, const float* __restrict__ k2,
                         const float* __restrict__ k3) {
    __shared__ float tile[32][33];
    int kt = blockIdx.x * 32, nt = blockIdx.y * 32;
    int tx = threadIdx.x, ty = threadIdx.y;
    #pragma unroll
    for (int i = 0; i < 32; i += 8) {
        int k = kt + ty + i, n = nt + tx;
        const float* src; int kr;
        if (k < Dd) { src = k1; kr = k; }
        else if (k < Dd + U) { src = k2; kr = k - Dd; }
        else { src = k3; kr = k - Dd - U; }
        tile[ty + i][tx] = src[(size_t)kr * N5 + n];
    }
    __syncthreads();
    #pragma unroll
    for (int i = 0; i < 32; i += 8) {
        int n = nt + ty + i, k = kt + tx;
        g_Wt[(size_t)n * KTOT + k] = __float2half(tile[tx][ty + i]);
    }
}
__global__ void ktrans_AG(const float* __restrict__ agg) {
    __shared__ float tile[32][33];
    int kt = blockIdx.x * 32, nt = blockIdx.y * 32;
    int tx = threadIdx.x, ty = threadIdx.y;
    #pragma unroll
    for (int i = 0; i < 32; i += 8)
        tile[ty + i][tx] = agg[(size_t)(kt + ty + i) * U + nt + tx];
    __syncthreads();
    #pragma unroll
    for (int i = 0; i < 32; i += 8) {
        int n = nt + ty + i, k = kt + tx;
        g_AGt[(size_t)n * N3 + k] = __float2half(tile[tx][ty + i]);
    }
}

__global__ void kinit_scalars(const float* a0, const float* b0, const float* a1, const float* b1,
                              const float* a2, const float* b2, const float* a3, const float* b3,
                              const float* a4, const float* b4, const float* a5, const float* b5) {
    __shared__ float sm[8];
    const float* as[6] = {a0, a1, a2, a3, a4, a5};
    const float* bs[6] = {b0, b1, b2, b3, b4, b5};
    for (int p = 0; p < 6; p++) {
        float s = 0.f;
        for (int i = threadIdx.x; i < U; i += 256) s += as[p][i] * bs[p][i];
        float tot = blk_reduce_sum(s, sm);
        if (threadIdx.x == 0) g_s[p] = tot;
        __syncthreads();
    }
}

__global__ void kinit_A(const float* __restrict__ x) {
    int b = blockIdx.x;
    for (int i = threadIdx.x; i < KTOT; i += 256)
        g_A16[b * KTOT + i] = __float2half((i < Dd) ? x[(size_t)(b * T) * Dd + i] : 0.f);
    for (int i = threadIdx.x; i < U; i += 256) g_c[b * U + i] = 0.f;
    if (b == 0 && threadIdx.x < T) {
        g_barA[threadIdx.x] = 0u;
        g_barB[threadIdx.x] = 0u;
        g_barC[threadIdx.x] = 0u;
        g_barD[threadIdx.x] = 0u;
    }
}

// ---------------- generic GEMM body (device fn, exact R12 config) --------------
template<int MODE>
__device__ __forceinline__ void gemm_body(uint32_t smb, int tid, int n0, int ks,
                                          const float* __restrict__ bias) {
    constexpr int LDK  = (MODE == 0) ? KTOT : N3;
    constexpr int NTOT = (MODE == 0) ? N5 : U;
    constexpr int KLEN = (MODE == 0) ? ZKLEN : FKLEN;
    constexpr int NC   = KLEN / KCH;

    const __half* Wp = (MODE == 0) ? g_Wt : g_AGt;
    const __half* Ap = (MODE == 0) ? g_A16 : g_O16;
    float* OUT = (MODE == 0) ? g_zp : g_fp;

    const int kbase = ks * KLEN;
    const int lane  = tid & 31;
    const int w     = tid >> 5;

    const __half* srcB[6];
    uint32_t dstO[6];
    #pragma unroll
    for (int i = 0; i < 6; i++) {
        int seg = tid + i * 256;
        if (seg < 512) {
            int r = seg >> 3, s = seg & 7;
            srcB[i] = Ap + (size_t)r * LDK + s * 8;
            dstO[i] = r * ROWB + s * 16;
        } else {
            int idx = seg - 512;
            int r = idx >> 3, s = idx & 7;
            srcB[i] = Wp + (size_t)(n0 + r) * LDK + s * 8;
            dstO[i] = A_BLK + r * ROWB + s * 16;
        }
    }
    auto load_chunk = [&](int kk, int stg) {
        const uint32_t bb = smb + stg * STG_BYTES;
        #pragma unroll
        for (int i = 0; i < 6; i++)
            cpasync16(bb + dstO[i], srcB[i] + kk);
        cp_commit();
    };

    const int mrow0 = (w & 1) * 32;
    const int nrow0 = (w >> 1) * 32;
    const int rA  = mrow0 + (lane & 15);
    const int scA = lane >> 4;
    const int rB  = nrow0 + ((lane >> 4) << 3) + (lane & 7);
    const int scB = (lane >> 3) & 1;

    float acc[2][4][4] = {};

    #pragma unroll
    for (int p = 0; p < 3; p++)
        if (p < NC) load_chunk(kbase + p * KCH, p);

    for (int c = 0; c < NC; c++) {
        int rem = NC - 1 - c;
        if (rem >= 2) cp_wait<2>(); else if (rem == 1) cp_wait<1>(); else cp_wait<0>();
        __syncthreads();
        if (c + 3 < NC) load_chunk(kbase + (c + 3) * KCH, (c + 3) % NSTG);

        const uint32_t bb = smb + (c % NSTG) * STG_BYTES;
        #pragma unroll
        for (int s16 = 0; s16 < 4; s16++) {
            const int kd = s16 * 2;
            uint32_t ah[2][4], bh[2][4];
            #pragma unroll
            for (int mi = 0; mi < 2; mi++)
                ldsm4(ah[mi], bb + (rA + mi * 16) * ROWB + (kd + scA) * 16);
            #pragma unroll
            for (int nj = 0; nj < 2; nj++)
                ldsm4(bh[nj], bb + A_BLK + (rB + nj * 16) * ROWB + (kd + scB) * 16);
            #pragma unroll
            for (int mi = 0; mi < 2; mi++)
                #pragma unroll
                for (int nf = 0; nf < 4; nf++)
                    mma16816(acc[mi][nf], ah[mi], &bh[nf >> 1][(nf & 1) * 2]);
        }
    }

    #pragma unroll
    for (int mi = 0; mi < 2; mi++) {
        #pragma unroll
        for (int nf = 0; nf < 4; nf++) {
            int row = mrow0 + mi * 16 + (lane >> 2);
            int col = n0 + nrow0 + nf * 8 + (lane & 3) * 2;
            float2 v0 = make_float2(acc[mi][nf][0], acc[mi][nf][1]);
            float2 v1 = make_float2(acc[mi][nf][2], acc[mi][nf][3]);
            if (MODE == 0 && ks == 0) {
                v0.x += bias[col]; v0.y += bias[col + 1];
                v1.x += bias[col]; v1.y += bias[col + 1];
            }
            *reinterpret_cast<float2*>(OUT + (size_t)(ks * Bsz + row) * NTOT + col) = v0;
            *reinterpret_cast<float2*>(OUT + (size_t)(ks * Bsz + row + 8) * NTOT + col) = v1;
        }
    }
}

// ---------------- gate body (device fn; L2-only reads) --------------------------
__device__ __forceinline__ void gate_body(int b, int tid) {
    __shared__ float sm[16];
    const int i0 = tid * 4;

    float uz[4], dz[4], rz[4];
    {
        #define LOAD3(off, out) {                                                   \
            float4 s0 = ldcg4(g_zp + (size_t)(0*Bsz+b)*N5 + (off));                    \
            float4 s1 = ldcg4(g_zp + (size_t)(1*Bsz+b)*N5 + (off));                    \
            float4 s2 = ldcg4(g_zp + (size_t)(2*Bsz+b)*N5 + (off));                    \
            out[0] = s0.x + s1.x + s2.x; out[1] = s0.y + s1.y + s2.y;                  \
            out[2] = s0.z + s1.z + s2.z; out[3] = s0.w + s1.w + s2.w; }
        LOAD3(i0,         uz)
        LOAD3(U + i0,     dz)
        LOAD3(2 * U + i0, rz)
        #undef LOAD3
    }

    float mx = fmaxf(fmaxf(uz[0], uz[1]), fmaxf(uz[2], uz[3]));
    mx = blk_reduce_max(mx, sm);
    float e[4], ls = 0.f;
    #pragma unroll
    for (int l = 0; l < 4; l++) { e[l] = expf(uz[l] - mx); ls += e[l]; }
    ScanRes s1 = blk_scan(ls, sm);
    float up[4];
    { float P = s1.excl, inv = 1.f / s1.total;
      #pragma unroll
      for (int l = 0; l < 4; l++) { P += e[l]; up[l] = P * inv; } }

    float mx2 = fmaxf(fmaxf(dz[0], dz[1]), fmaxf(dz[2], dz[3]));
    mx2 = blk_reduce_max(mx2, sm);
    float ed[4]; ls = 0.f;
    #pragma unroll
    for (int l = 0; l < 4; l++) { ed[l] = expf(dz[l] - mx2); ls += ed[l]; }
    ScanRes s2 = blk_scan(ls, sm);
    float dn[4];
    { float P = s2.excl, inv = 1.f / s2.total;
      #pragma unroll
      for (int l = 0; l < 4; l++) { P += ed[l]; dn[l] = (s2.total - P + ed[l]) * inv; } }

    float pdu = 0.f, pru = 0.f, pdr = 0.f;
    #pragma unroll
    for (int l = 0; l < 4; l++) { pdu += dn[l] * up[l]; pru += rz[l] * up[l]; pdr += dn[l] * rz[l]; }
    float du = blk_reduce_sum(pdu, sm);
    float ru = blk_reduce_sum(pru, sm);
    float dr = blk_reduce_sum(pdr, sm);

    const float s_ud = g_s[0], s_ur = g_s[1], s_ru = g_s[2];
    const float s_rd = g_s[3], s_du = g_s[4], s_dr = g_s[5];

    #pragma unroll
    for (int l = 0; l < 4; l++) {
        float t1 = sigf(s_ud * up[l] * du) + sigf(s_ur * up[l] * ru);
        float t2 = sigf(s_ru * rz[l] * ru) + sigf(s_rd * rz[l] * dr);
        float t3 = sigf(s_du * dn[l] * du) + sigf(s_dr * dn[l] * dr);
        g_O16[b * N3 + i0 + l]         = __float2half(t1);
        g_O16[b * N3 + U + i0 + l]     = __float2half(t2);
        g_O16[b * N3 + 2 * U + i0 + l] = __float2half(t3);
    }
}

// ---------------- update body (device fn; L2-only reads of shared bufs) ---------
__device__ __forceinline__ void update_body(int b, int tid, int t,
                                            const float* __restrict__ x,
                                            float* __restrict__ out) {
    const int j0 = tid * 4;
    {
        int j = j0;
        float4 fs = make_float4(0.f, 0.f, 0.f, 0.f);
        #pragma unroll
        for (int ks = 0; ks < FSPLIT; ks++) {
            float4 p = ldcg4(g_fp + (size_t)(ks * Bsz + b) * U + j);
            fs.x += p.x; fs.y += p.y; fs.z += p.z; fs.w += p.w;
        }
        float4 og = make_float4(0.f, 0.f, 0.f, 0.f), zc = og;
        #pragma unroll
        for (int ks = 0; ks < ZSPLIT; ks++) {
            float4 p = ldcg4(g_zp + (size_t)(ks * Bsz + b) * N5 + 3 * U + j);
            og.x += p.x; og.y += p.y; og.z += p.z; og.w += p.w;
            p = ldcg4(g_zp + (size_t)(ks * Bsz + b) * N5 + 4 * U + j);
            zc.x += p.x; zc.y += p.y; zc.z += p.z; zc.w += p.w;
        }
        float fv[4] = {fs.x, fs.y, fs.z, fs.w};
        float ov[4] = {og.x, og.y, og.z, og.w};
        float zv[4] = {zc.x, zc.y, zc.z, zc.w};
        float cn[4], hn[4];
        #pragma unroll
        for (int l = 0; l < 4; l++) {
            float f  = sigf(fv[l]);
            float ci = tanhf(zv[l]);
            float co = g_c[(size_t)b * U + j + l];
            cn[l] = f * co + (1.f - f) * ci;
            hn[l] = ov[l] * tanhf(cn[l]);
            g_c[(size_t)b * U + j + l] = cn[l];
            out[((size_t)b * T + t) * U + j + l] = hn[l];
            g_A16[b * KTOT + Dd + j + l]     = __float2half(hn[l]);
            g_A16[b * KTOT + Dd + U + j + l] = __float2half(cn[l]);
        }
    }
    if (t + 1 < T && tid < 64) {
        #pragma unroll
        for (int l = 0; l < 4; l++) {
            int d = tid * 4 + l;
            g_A16[b * KTOT + d] = __float2half(x[((size_t)b * T + (t + 1)) * Dd + d]);
        }
    }
}

// ---------------- persistent scan kernel: 120 CTAs, whole T loop ----------------
__global__ void __launch_bounds__(256) k_scan(const float* __restrict__ bias,
                                              const float* __restrict__ x,
                                              float* __restrict__ out) {
    const int bid = blockIdx.x, tid = threadIdx.x;
    extern __shared__ char dyn[];
    const uint32_t smb = smem_u32(dyn);

    const int n0z = (bid % 40) * NTILE, ksz = bid / 40;
    const int n0f = (bid % 8) * NTILE,  ksf = bid / 8;

    for (int t = 0; t < T; t++) {
        // phase 1: z-GEMM on all 120 CTAs
        gemm_body<0>(smb, tid, n0z, ksz, bias);
        gbarN(&g_barA[t], tid, NCTA);

        if (bid < FCTAS) {
            // phase 2: gates on CTAs 0..63
            if (bid < Bsz) gate_body(bid, tid);
            gbarN(&g_barB[t], tid, FCTAS);
            // phase 3: agg-GEMM on CTAs 0..95
            gemm_body<1>(smb, tid, n0f, ksf, nullptr);
            gbarN(&g_barC[t], tid, FCTAS);
            // phase 4: update on CTAs 0..63
            if (bid < Bsz) update_body(bid, tid, t, x, out);
        }
        gbarN(&g_barD[t], tid, NCTA);
    }
}

// ---------------- launch ---------------------------------------------------------
extern "C" void kernel_launch(void* const* d_in, const int* in_sizes, int n_in,
                              void* d_out, int out_size) {
    const float* x    = (const float*)d_in[0];
    const float* kern = (const float*)d_in[1];
    const float* rker = (const float*)d_in[2];
    const float* cker = (const float*)d_in[3];
    const float* bias = (const float*)d_in[4];
    const float* agg  = (const float*)d_in[5];
    float* out = (float*)d_out;

    cudaFuncSetAttribute(k_scan, cudaFuncAttributeMaxDynamicSharedMemorySize, GSMEM_BYTES);

    ktrans_W <<<dim3(KTOT / 32, N5 / 32), dim3(32, 8)>>>(kern, rker, cker);
    ktrans_AG<<<dim3(N3 / 32,  U  / 32), dim3(32, 8)>>>(agg);
    kinit_scalars<<<1, 256>>>((const float*)d_in[6],  (const float*)d_in[7],
                              (const float*)d_in[8],  (const float*)d_in[9],
                              (const float*)d_in[10], (const float*)d_in[11],
                              (const float*)d_in[12], (const float*)d_in[13],
                              (const float*)d_in[14], (const float*)d_in[15],
                              (const float*)d_in[16], (const float*)d_in[17]);
    kinit_A<<<Bsz, 256>>>(x);

    k_scan<<<NCTA, 256, GSMEM_BYTES>>>(bias, x, out);
}